// round 8
// baseline (speedup 1.0000x reference)
#include <cuda_runtime.h>
#include <cuda_fp16.h>
#include <cstdint>

#define Bx 4
#define Nx 4096
#define Cx 1024
#define NC3 3072
#define EPSV 1e-15f

// Scratch (device globals — no allocation allowed).  fp16 planes pack 2
// elems per uint32 word, row-major [rows][K/2 words].
__device__ float    g_qkv[(size_t)Bx * Nx * NC3];          // 192 MB fp32
__device__ uint32_t g_xh[(size_t)Bx * Nx * Cx / 2];
__device__ uint32_t g_xl[(size_t)Bx * Nx * Cx / 2];
__device__ uint32_t g_ath[(size_t)Bx * Nx * Cx / 2];
__device__ uint32_t g_atl[(size_t)Bx * Nx * Cx / 2];
__device__ uint32_t g_wqh[(size_t)NC3 * Cx / 2];
__device__ uint32_t g_wph[(size_t)Cx * Cx / 2];
__device__ float    g_vkpart[1024 * 1056];
__device__ float    g_vk[128 * 1056];

__device__ __forceinline__ uint32_t smem_u32(const void* p) {
    uint32_t a;
    asm("{ .reg .u64 t; cvta.to.shared.u64 t, %1; cvt.u32.u64 %0, t; }"
        : "=r"(a) : "l"(p));
    return a;
}
__device__ __forceinline__ void cpa16(uint32_t s, const void* g) {
    asm volatile("cp.async.cg.shared.global [%0], [%1], 16;"
                 :: "r"(s), "l"(g) : "memory");
}
__device__ __forceinline__ void ldsm4(uint32_t& r0, uint32_t& r1,
                                      uint32_t& r2, uint32_t& r3, uint32_t a) {
    asm volatile("ldmatrix.sync.aligned.m8n8.x4.shared.b16 {%0,%1,%2,%3}, [%4];"
                 : "=r"(r0), "=r"(r1), "=r"(r2), "=r"(r3) : "r"(a));
}
__device__ __forceinline__ void mma_f16(float d[4], const uint32_t a[4],
                                        uint32_t b0, uint32_t b1) {
    asm("mma.sync.aligned.m16n8k16.row.col.f32.f16.f16.f32 "
        "{%0,%1,%2,%3}, {%4,%5,%6,%7}, {%8,%9}, {%0,%1,%2,%3};"
        : "+f"(d[0]), "+f"(d[1]), "+f"(d[2]), "+f"(d[3])
        : "r"(a[0]), "r"(a[1]), "r"(a[2]), "r"(a[3]), "r"(b0), "r"(b1));
}
__device__ __forceinline__ void split_pair(float e0, float e1,
                                           uint32_t& hw, uint32_t& lw) {
    __half h0 = __float2half_rn(e0);
    __half h1 = __float2half_rn(e1);
    float r0 = e0 - __half2float(h0);
    float r1 = e1 - __half2float(h1);
    __half2 hp = __halves2half2(h0, h1);
    __half2 lp = __halves2half2(__float2half_rn(r0), __float2half_rn(r1));
    hw = *(uint32_t*)&hp;
    lw = *(uint32_t*)&lp;
}

__global__ void split2_kernel(const float* __restrict__ in,
                              uint32_t* __restrict__ oh,
                              uint32_t* __restrict__ ol, int npairs)
{
    int i = blockIdx.x * 256 + threadIdx.x;
    if (i >= npairs) return;
    float2 v = ((const float2*)in)[i];
    uint32_t hw, lw;
    split_pair(v.x, v.y, hw, lw);
    oh[i] = hw;
    ol[i] = lw;
}

__global__ void round1_kernel(const float* __restrict__ in,
                              uint32_t* __restrict__ oh, int npairs)
{
    int i = blockIdx.x * 256 + threadIdx.x;
    if (i >= npairs) return;
    float2 v = ((const float2*)in)[i];
    __half2 hp = __halves2half2(__float2half_rn(v.x), __float2half_rn(v.y));
    oh[i] = *(uint32_t*)&hp;
}

// ---------------------------------------------------------------------------
// fp16 A-split 2-chain GEMM:  C[m,n] = sum_k A[m,k]*W[n,k]
// A given as hi/lo fp16 planes; W single-rounded fp16.
// CTA 128x128x32, 4 warps (128 thr), warp tile 64x64, ldmatrix,
// 3-stage cp.async, 2 CTAs/SM.  MODE 0: relu n<relu_upto. MODE 1: +bias.
// ---------------------------------------------------------------------------
template <int MODE>
__global__ __launch_bounds__(128, 2) void f16_gemm(
    const uint32_t* __restrict__ Ah_, const uint32_t* __restrict__ Al_,
    const uint32_t* __restrict__ Wh_,
    float* __restrict__ C, const float* __restrict__ bias,
    int M, int Nn, int K, int relu_upto)
{
    constexpr int PITCH = 80;
    constexpr int A_TILE = 128 * PITCH;          // 10240
    constexpr int OFF_AL = A_TILE;
    constexpr int OFF_B  = 2 * A_TILE;
    constexpr int STAGE  = 3 * A_TILE;           // 30720
    extern __shared__ char smem[];
    const uint32_t sb = smem_u32(smem);

    const int tid = threadIdx.x;
    const int wid = tid >> 5;
    const int lane = tid & 31;
    const int g = lane >> 2;
    const int tig = lane & 3;
    const int warp_m = (wid & 1) * 64;
    const int warp_n = (wid >> 1) * 64;
    const int m0 = blockIdx.y * 128;
    const int n0 = blockIdx.x * 128;

    const __half* Ah = (const __half*)Ah_;
    const __half* Al = (const __half*)Al_;
    const __half* Wh = (const __half*)Wh_;

    float acc[4][8][4];
#pragma unroll
    for (int mt = 0; mt < 4; mt++)
#pragma unroll
        for (int nt = 0; nt < 8; nt++)
#pragma unroll
            for (int j = 0; j < 4; j++) acc[mt][nt][j] = 0.0f;

    const int NK = K / 32;
    const int crow = tid >> 2;                   // 0..31
    const int cchk = tid & 3;                    // 16B chunk (8 halfs)

    auto issue = [&](int it, int s) {
        const int kt = it * 32 + cchk * 8;
        const uint32_t st = sb + (uint32_t)s * STAGE;
#pragma unroll
        for (int i = 0; i < 4; i++) {
            int r = crow + i * 32;
            uint32_t so = (uint32_t)(r * PITCH + cchk * 16);
            const size_t ga = (size_t)(m0 + r) * K + kt;
            cpa16(st + so, Ah + ga);
            cpa16(st + OFF_AL + so, Al + ga);
            cpa16(st + OFF_B + so, Wh + (size_t)(n0 + r) * K + kt);
        }
        asm volatile("cp.async.commit_group;" ::: "memory");
    };

    issue(0, 0);
    if (NK > 1) issue(1, 1);

    const uint32_t lrow = (uint32_t)(lane & 15);
    const uint32_t lchk = (uint32_t)(lane >> 4) * 16;

    for (int it = 0; it < NK; it++) {
        if (it + 1 < NK) {
            asm volatile("cp.async.wait_group 1;" ::: "memory");
        } else {
            asm volatile("cp.async.wait_group 0;" ::: "memory");
        }
        __syncthreads();
        if (it + 2 < NK) issue(it + 2, (it + 2) % 3);

        const uint32_t st = sb + (uint32_t)(it % 3) * STAGE;
        const uint32_t abase = st + (uint32_t)(warp_m + lrow) * PITCH + lchk;
        const uint32_t bbase = st + OFF_B + (uint32_t)(warp_n + lrow) * PITCH + lchk;

#pragma unroll
        for (int kk = 0; kk < 2; kk++) {
            uint32_t ah[4][4], al[4][4];
#pragma unroll
            for (int mt = 0; mt < 4; mt++) {
                uint32_t ao = abase + (uint32_t)(mt * 16 * PITCH + kk * 32);
                ldsm4(ah[mt][0], ah[mt][1], ah[mt][2], ah[mt][3], ao);
                ldsm4(al[mt][0], al[mt][1], al[mt][2], al[mt][3], ao + OFF_AL);
            }
            uint32_t b[8][2];
#pragma unroll
            for (int p = 0; p < 4; p++) {
                uint32_t bo = bbase + (uint32_t)(p * 16 * PITCH + kk * 32);
                uint32_t r0, r1, r2, r3;
                ldsm4(r0, r1, r2, r3, bo);
                b[2 * p][0] = r0; b[2 * p][1] = r2;
                b[2 * p + 1][0] = r1; b[2 * p + 1][1] = r3;
            }
#pragma unroll
            for (int nt = 0; nt < 8; nt++)
#pragma unroll
                for (int mt = 0; mt < 4; mt++)
                    mma_f16(acc[mt][nt], ah[mt], b[nt][0], b[nt][1]);
#pragma unroll
            for (int nt = 0; nt < 8; nt++)
#pragma unroll
                for (int mt = 0; mt < 4; mt++)
                    mma_f16(acc[mt][nt], al[mt], b[nt][0], b[nt][1]);
        }
    }

    // epilogue (fp32 out)
#pragma unroll
    for (int mt = 0; mt < 4; mt++) {
        int mA = m0 + warp_m + mt * 16 + g;
#pragma unroll
        for (int nt = 0; nt < 8; nt++) {
            int n = n0 + warp_n + nt * 8 + 2 * tig;
            float e0 = acc[mt][nt][0], e1 = acc[mt][nt][1];
            float e2 = acc[mt][nt][2], e3 = acc[mt][nt][3];
            if (MODE == 0) {
                if (n < relu_upto)     { e0 = fmaxf(e0, 0.f); e2 = fmaxf(e2, 0.f); }
                if (n + 1 < relu_upto) { e1 = fmaxf(e1, 0.f); e3 = fmaxf(e3, 0.f); }
            } else {
                float bb0 = bias[n], bb1 = bias[n + 1];
                e0 += bb0; e1 += bb1; e2 += bb0; e3 += bb1;
            }
            *(float2*)(C + (size_t)mA * Nn + n)       = make_float2(e0, e1);
            *(float2*)(C + (size_t)(mA + 8) * Nn + n) = make_float2(e2, e3);
        }
    }
}

// ---------------------------------------------------------------------------
// vk partial reduction (unchanged)
// ---------------------------------------------------------------------------
__global__ __launch_bounds__(256) void vk_partial_kernel(
    const float* __restrict__ qkv, float* __restrict__ part)
{
    const int blk = blockIdx.x;
    const int slice = blk & 7;
    const int head = blk >> 3;
    const int b = head >> 5;
    const int hh = head & 31;
    const int tid = threadIdx.x;

    __shared__ float ks[8][32];
    __shared__ float vs[8][32];

    float acc[5] = {0.f, 0.f, 0.f, 0.f, 0.f};

    const float* base = qkv + (size_t)b * Nx * NC3 + (size_t)(slice * 512) * NC3 + hh * 32;
    const int r = tid >> 5;
    const int e = tid & 31;

    for (int n0 = 0; n0 < 512; n0 += 8) {
        const float* p = base + (size_t)(n0 + r) * NC3 + e;
        float kreg = p[1024];
        float vreg = p[2048];
        __syncthreads();
        ks[r][e] = kreg;
        vs[r][e] = vreg;
        __syncthreads();
#pragma unroll
        for (int rr = 0; rr < 8; rr++) {
#pragma unroll
            for (int i = 0; i < 5; i++) {
                int idx = tid + 256 * i;
                if (idx < 1056) {
                    int d = idx >> 5;
                    int ee = idx & 31;
                    float vval = (d == 32) ? 1.0f : vs[rr][d];
                    acc[i] += vval * ks[rr][ee];
                }
            }
        }
    }
#pragma unroll
    for (int i = 0; i < 5; i++) {
        int idx = tid + 256 * i;
        if (idx < 1056) part[(size_t)blk * 1056 + idx] = acc[i];
    }
}

__global__ void vk_reduce_kernel(const float* __restrict__ part,
                                 float* __restrict__ vk)
{
    int idx = blockIdx.x * 256 + threadIdx.x;
    if (idx >= 128 * 1056) return;
    int head = idx / 1056;
    int j = idx % 1056;
    float s = 0.f;
#pragma unroll
    for (int sl = 0; sl < 8; sl++)
        s += part[(size_t)(head * 8 + sl) * 1056 + j];
    vk[idx] = s;
}

// ---------------------------------------------------------------------------
// att kernel: normalize, write split fp16 hi/lo planes (GEMM2 A operand)
// ---------------------------------------------------------------------------
__global__ __launch_bounds__(128) void att_kernel(
    const float* __restrict__ qkv, const float* __restrict__ vk,
    uint32_t* __restrict__ ath, uint32_t* __restrict__ atl)
{
    const int blk = blockIdx.x;
    const int nch = blk & 31;
    const int head = blk >> 5;
    const int b = head >> 5;
    const int hh = head & 31;
    const int tid = threadIdx.x;

    __shared__ float vks[1056];
    __shared__ float qs[128][33];
    __shared__ uint32_t sh[128][17];
    __shared__ uint32_t sl[128][17];

    for (int i = tid; i < 1056; i += 128)
        vks[i] = vk[(size_t)head * 1056 + i];

    const float* qbase = qkv + (size_t)b * Nx * NC3 + (size_t)(nch * 128) * NC3 + hh * 32;
#pragma unroll
    for (int i = 0; i < 32; i++) {
        int idx = i * 128 + tid;
        int row = idx >> 5;
        int e = idx & 31;
        qs[row][e] = qbase[(size_t)row * NC3 + e];
    }
    __syncthreads();

    float qr[32];
#pragma unroll
    for (int e = 0; e < 32; e++) qr[e] = qs[tid][e];

    float den = 0.f;
#pragma unroll
    for (int e = 0; e < 32; e++) den += vks[1024 + e] * qr[e];
    float inv = 1.0f / (den + EPSV);

#pragma unroll
    for (int w = 0; w < 16; w++) {
        float s0 = 0.f, s1 = 0.f;
#pragma unroll
        for (int e = 0; e < 32; e++) {
            s0 += vks[(2 * w) * 32 + e] * qr[e];
            s1 += vks[(2 * w + 1) * 32 + e] * qr[e];
        }
        uint32_t hw, lw;
        split_pair(s0 * inv, s1 * inv, hw, lw);
        sh[tid][w] = hw;
        sl[tid][w] = lw;
    }
    __syncthreads();

    const size_t rowbase = (size_t)b * Nx + (size_t)nch * 128;
#pragma unroll
    for (int i = 0; i < 16; i++) {
        int idx = i * 128 + tid;
        int row = idx >> 4;
        int w = idx & 15;
        size_t o = (rowbase + row) * 512 + hh * 16 + w;
        ath[o] = sh[row][w];
        atl[o] = sl[row][w];
    }
}

// ---------------------------------------------------------------------------
extern "C" void kernel_launch(void* const* d_in, const int* in_sizes, int n_in,
                              void* d_out, int out_size)
{
    const float* x     = (const float*)d_in[0];
    const float* Wqkv  = (const float*)d_in[1];
    const float* Wproj = (const float*)d_in[2];
    const float* bproj = (const float*)d_in[3];
    float* out = (float*)d_out;

    float *qkv, *part, *vk;
    uint32_t *xh, *xl, *ath, *atl, *wqh, *wph;
    cudaGetSymbolAddress((void**)&qkv,  g_qkv);
    cudaGetSymbolAddress((void**)&part, g_vkpart);
    cudaGetSymbolAddress((void**)&vk,   g_vk);
    cudaGetSymbolAddress((void**)&xh,   g_xh);
    cudaGetSymbolAddress((void**)&xl,   g_xl);
    cudaGetSymbolAddress((void**)&ath,  g_ath);
    cudaGetSymbolAddress((void**)&atl,  g_atl);
    cudaGetSymbolAddress((void**)&wqh,  g_wqh);
    cudaGetSymbolAddress((void**)&wph,  g_wph);

    const int M = Bx * Nx;   // 16384

    const int smem = 3 * 30720;   // 92160 B per CTA (2 CTAs/SM)
    cudaFuncSetAttribute(f16_gemm<0>,
                         cudaFuncAttributeMaxDynamicSharedMemorySize, smem);
    cudaFuncSetAttribute(f16_gemm<1>,
                         cudaFuncAttributeMaxDynamicSharedMemorySize, smem);

    // 0) operand prep: x -> hi/lo fp16 planes, weights -> single fp16
    {
        int np;
        np = M * Cx / 2;
        split2_kernel<<<(np + 255) / 256, 256>>>(x, xh, xl, np);
        np = NC3 * Cx / 2;
        round1_kernel<<<(np + 255) / 256, 256>>>(Wqkv, wqh, np);
        np = Cx * Cx / 2;
        round1_kernel<<<(np + 255) / 256, 256>>>(Wproj, wph, np);
    }

    // 1) qkv = x @ Wqkv^T (fp16 A-split 2-chain), relu on n < 2048
    f16_gemm<0><<<dim3(NC3 / 128, M / 128), 128, smem>>>(
        xh, xl, wqh, qkv, nullptr, M, NC3, Cx, 2 * Cx);

    // 2) vk partials + reduce
    vk_partial_kernel<<<1024, 256>>>(qkv, part);
    vk_reduce_kernel<<<(128 * 1056 + 255) / 256, 256>>>(part, vk);

    // 3) attention normalize -> att hi/lo planes
    att_kernel<<<4096, 128>>>(qkv, vk, ath, atl);

    // 4) out = att @ Wproj^T + b  (fp16 A-split 2-chain)
    f16_gemm<1><<<dim3(Cx / 128, M / 128), 128, smem>>>(
        ath, atl, wph, out, bproj, M, Cx, Cx, 0);
}

// round 9
// speedup vs baseline: 1.2685x; 1.2685x over previous
#include <cuda_runtime.h>
#include <cuda_fp16.h>
#include <cstdint>

#define Bx 4
#define Nx 4096
#define Cx 1024
#define NC3 3072
#define EPSV 1e-15f

// Scratch (device globals — no allocation allowed).  fp16 planes pack 2
// elems per uint32 word, row-major [rows][K/2 words].
__device__ float    g_qkv[(size_t)Bx * Nx * NC3];          // 192 MB fp32
__device__ uint32_t g_xh[(size_t)Bx * Nx * Cx / 2];
__device__ uint32_t g_xl[(size_t)Bx * Nx * Cx / 2];
__device__ uint32_t g_ath[(size_t)Bx * Nx * Cx / 2];       // att single fp16
__device__ uint32_t g_wqh[(size_t)NC3 * Cx / 2];
__device__ uint32_t g_wph[(size_t)Cx * Cx / 2];
__device__ float    g_vkpart[1024 * 1056];
__device__ float    g_vk[128 * 1056];

__device__ __forceinline__ uint32_t smem_u32(const void* p) {
    uint32_t a;
    asm("{ .reg .u64 t; cvta.to.shared.u64 t, %1; cvt.u32.u64 %0, t; }"
        : "=r"(a) : "l"(p));
    return a;
}
__device__ __forceinline__ void cpa16(uint32_t s, const void* g) {
    asm volatile("cp.async.cg.shared.global [%0], [%1], 16;"
                 :: "r"(s), "l"(g) : "memory");
}
__device__ __forceinline__ void ldsm4(uint32_t& r0, uint32_t& r1,
                                      uint32_t& r2, uint32_t& r3, uint32_t a) {
    asm volatile("ldmatrix.sync.aligned.m8n8.x4.shared.b16 {%0,%1,%2,%3}, [%4];"
                 : "=r"(r0), "=r"(r1), "=r"(r2), "=r"(r3) : "r"(a));
}
__device__ __forceinline__ void mma_f16(float d[4], const uint32_t a[4],
                                        uint32_t b0, uint32_t b1) {
    asm("mma.sync.aligned.m16n8k16.row.col.f32.f16.f16.f32 "
        "{%0,%1,%2,%3}, {%4,%5,%6,%7}, {%8,%9}, {%0,%1,%2,%3};"
        : "+f"(d[0]), "+f"(d[1]), "+f"(d[2]), "+f"(d[3])
        : "r"(a[0]), "r"(a[1]), "r"(a[2]), "r"(a[3]), "r"(b0), "r"(b1));
}
__device__ __forceinline__ void split_pair(float e0, float e1,
                                           uint32_t& hw, uint32_t& lw) {
    __half h0 = __float2half_rn(e0);
    __half h1 = __float2half_rn(e1);
    float r0 = e0 - __half2float(h0);
    float r1 = e1 - __half2float(h1);
    __half2 hp = __halves2half2(h0, h1);
    __half2 lp = __halves2half2(__float2half_rn(r0), __float2half_rn(r1));
    hw = *(uint32_t*)&hp;
    lw = *(uint32_t*)&lp;
}

__global__ void split2_kernel(const float* __restrict__ in,
                              uint32_t* __restrict__ oh,
                              uint32_t* __restrict__ ol, int npairs)
{
    int i = blockIdx.x * 256 + threadIdx.x;
    if (i >= npairs) return;
    float2 v = ((const float2*)in)[i];
    uint32_t hw, lw;
    split_pair(v.x, v.y, hw, lw);
    oh[i] = hw;
    ol[i] = lw;
}

__global__ void round1_kernel(const float* __restrict__ in,
                              uint32_t* __restrict__ oh, int npairs)
{
    int i = blockIdx.x * 256 + threadIdx.x;
    if (i >= npairs) return;
    float2 v = ((const float2*)in)[i];
    __half2 hp = __halves2half2(__float2half_rn(v.x), __float2half_rn(v.y));
    oh[i] = *(uint32_t*)&hp;
}

// ---------------------------------------------------------------------------
// fp16 GEMM:  C[m,n] = sum_k A[m,k]*W[n,k]
// NCHAIN=2: A given as hi/lo fp16 planes (chained); NCHAIN=1: hi only.
// W single-rounded fp16.  CTA 128x128x32, 8 warps, warp tile 32x64,
// ldmatrix, 3-stage cp.async, 2 CTAs/SM.
// MODE 0: relu on n < relu_upto.  MODE 1: add bias[n].
// ---------------------------------------------------------------------------
template <int NCHAIN, int MODE>
__global__ __launch_bounds__(256, 2) void f16_gemm(
    const uint32_t* __restrict__ Ah_, const uint32_t* __restrict__ Al_,
    const uint32_t* __restrict__ Wh_,
    float* __restrict__ C, const float* __restrict__ bias,
    int M, int Nn, int K, int relu_upto)
{
    constexpr int PITCH = 80;
    constexpr int A_TILE = 128 * PITCH;              // 10240
    constexpr int OFF_AL = A_TILE;                   // only if NCHAIN==2
    constexpr int OFF_B  = NCHAIN == 2 ? 2 * A_TILE : A_TILE;
    constexpr int STAGE  = (NCHAIN + 1) * A_TILE;
    extern __shared__ char smem[];
    const uint32_t sb = smem_u32(smem);

    const int tid = threadIdx.x;
    const int wid = tid >> 5;
    const int lane = tid & 31;
    const int g = lane >> 2;
    const int tig = lane & 3;
    const int warp_m = (wid & 3) * 32;
    const int warp_n = (wid >> 2) * 64;
    const int m0 = blockIdx.y * 128;
    const int n0 = blockIdx.x * 128;

    const __half* Ah = (const __half*)Ah_;
    const __half* Al = (const __half*)Al_;
    const __half* Wh = (const __half*)Wh_;

    float acc[2][8][4];
#pragma unroll
    for (int mt = 0; mt < 2; mt++)
#pragma unroll
        for (int nt = 0; nt < 8; nt++)
#pragma unroll
            for (int j = 0; j < 4; j++) acc[mt][nt][j] = 0.0f;

    const int NK = K / 32;
    const int crow = tid >> 2;                       // 0..63
    const int cchk = tid & 3;                        // 16B chunk (8 halfs)

    auto issue = [&](int it, int s) {
        const int kt = it * 32 + cchk * 8;
        const uint32_t st = sb + (uint32_t)s * STAGE;
#pragma unroll
        for (int i = 0; i < 2; i++) {
            int r = crow + i * 64;
            uint32_t so = (uint32_t)(r * PITCH + cchk * 16);
            const size_t ga = (size_t)(m0 + r) * K + kt;
            cpa16(st + so, Ah + ga);
            if (NCHAIN == 2) cpa16(st + OFF_AL + so, Al + ga);
            cpa16(st + OFF_B + so, Wh + (size_t)(n0 + r) * K + kt);
        }
        asm volatile("cp.async.commit_group;" ::: "memory");
    };

    issue(0, 0);
    if (NK > 1) issue(1, 1);

    const uint32_t lrow = (uint32_t)(lane & 15);
    const uint32_t lchk = (uint32_t)(lane >> 4) * 16;

    for (int it = 0; it < NK; it++) {
        if (it + 1 < NK) {
            asm volatile("cp.async.wait_group 1;" ::: "memory");
        } else {
            asm volatile("cp.async.wait_group 0;" ::: "memory");
        }
        __syncthreads();
        if (it + 2 < NK) issue(it + 2, (it + 2) % 3);

        const uint32_t st = sb + (uint32_t)(it % 3) * STAGE;
        const uint32_t abase = st + (uint32_t)(warp_m + lrow) * PITCH + lchk;
        const uint32_t bbase = st + OFF_B + (uint32_t)(warp_n + lrow) * PITCH + lchk;

#pragma unroll
        for (int kk = 0; kk < 2; kk++) {
            uint32_t ah[2][4], al[2][4];
#pragma unroll
            for (int mt = 0; mt < 2; mt++) {
                uint32_t ao = abase + (uint32_t)(mt * 16 * PITCH + kk * 32);
                ldsm4(ah[mt][0], ah[mt][1], ah[mt][2], ah[mt][3], ao);
                if (NCHAIN == 2)
                    ldsm4(al[mt][0], al[mt][1], al[mt][2], al[mt][3], ao + OFF_AL);
            }
            uint32_t b[8][2];
#pragma unroll
            for (int p = 0; p < 4; p++) {
                uint32_t bo = bbase + (uint32_t)(p * 16 * PITCH + kk * 32);
                uint32_t r0, r1, r2, r3;
                ldsm4(r0, r1, r2, r3, bo);
                b[2 * p][0] = r0; b[2 * p][1] = r2;
                b[2 * p + 1][0] = r1; b[2 * p + 1][1] = r3;
            }
#pragma unroll
            for (int nt = 0; nt < 8; nt++)
#pragma unroll
                for (int mt = 0; mt < 2; mt++)
                    mma_f16(acc[mt][nt], ah[mt], b[nt][0], b[nt][1]);
            if (NCHAIN == 2) {
#pragma unroll
                for (int nt = 0; nt < 8; nt++)
#pragma unroll
                    for (int mt = 0; mt < 2; mt++)
                        mma_f16(acc[mt][nt], al[mt], b[nt][0], b[nt][1]);
            }
        }
    }

    // epilogue (fp32 out)
#pragma unroll
    for (int mt = 0; mt < 2; mt++) {
        int mA = m0 + warp_m + mt * 16 + g;
#pragma unroll
        for (int nt = 0; nt < 8; nt++) {
            int n = n0 + warp_n + nt * 8 + 2 * tig;
            float e0 = acc[mt][nt][0], e1 = acc[mt][nt][1];
            float e2 = acc[mt][nt][2], e3 = acc[mt][nt][3];
            if (MODE == 0) {
                if (n < relu_upto)     { e0 = fmaxf(e0, 0.f); e2 = fmaxf(e2, 0.f); }
                if (n + 1 < relu_upto) { e1 = fmaxf(e1, 0.f); e3 = fmaxf(e3, 0.f); }
            } else {
                float bb0 = bias[n], bb1 = bias[n + 1];
                e0 += bb0; e1 += bb1; e2 += bb0; e3 += bb1;
            }
            *(float2*)(C + (size_t)mA * Nn + n)       = make_float2(e0, e1);
            *(float2*)(C + (size_t)(mA + 8) * Nn + n) = make_float2(e2, e3);
        }
    }
}

// ---------------------------------------------------------------------------
// vk partial reduction (unchanged)
// ---------------------------------------------------------------------------
__global__ __launch_bounds__(256) void vk_partial_kernel(
    const float* __restrict__ qkv, float* __restrict__ part)
{
    const int blk = blockIdx.x;
    const int slice = blk & 7;
    const int head = blk >> 3;
    const int b = head >> 5;
    const int hh = head & 31;
    const int tid = threadIdx.x;

    __shared__ float ks[8][32];
    __shared__ float vs[8][32];

    float acc[5] = {0.f, 0.f, 0.f, 0.f, 0.f};

    const float* base = qkv + (size_t)b * Nx * NC3 + (size_t)(slice * 512) * NC3 + hh * 32;
    const int r = tid >> 5;
    const int e = tid & 31;

    for (int n0 = 0; n0 < 512; n0 += 8) {
        const float* p = base + (size_t)(n0 + r) * NC3 + e;
        float kreg = p[1024];
        float vreg = p[2048];
        __syncthreads();
        ks[r][e] = kreg;
        vs[r][e] = vreg;
        __syncthreads();
#pragma unroll
        for (int rr = 0; rr < 8; rr++) {
#pragma unroll
            for (int i = 0; i < 5; i++) {
                int idx = tid + 256 * i;
                if (idx < 1056) {
                    int d = idx >> 5;
                    int ee = idx & 31;
                    float vval = (d == 32) ? 1.0f : vs[rr][d];
                    acc[i] += vval * ks[rr][ee];
                }
            }
        }
    }
#pragma unroll
    for (int i = 0; i < 5; i++) {
        int idx = tid + 256 * i;
        if (idx < 1056) part[(size_t)blk * 1056 + idx] = acc[i];
    }
}

__global__ void vk_reduce_kernel(const float* __restrict__ part,
                                 float* __restrict__ vk)
{
    int idx = blockIdx.x * 256 + threadIdx.x;
    if (idx >= 128 * 1056) return;
    int head = idx / 1056;
    int j = idx % 1056;
    float s = 0.f;
#pragma unroll
    for (int sl = 0; sl < 8; sl++)
        s += part[(size_t)(head * 8 + sl) * 1056 + j];
    vk[idx] = s;
}

// ---------------------------------------------------------------------------
// att kernel: normalize, write single fp16 plane (GEMM2 A operand)
// ---------------------------------------------------------------------------
__global__ __launch_bounds__(128) void att_kernel(
    const float* __restrict__ qkv, const float* __restrict__ vk,
    uint32_t* __restrict__ ath)
{
    const int blk = blockIdx.x;
    const int nch = blk & 31;
    const int head = blk >> 5;
    const int b = head >> 5;
    const int hh = head & 31;
    const int tid = threadIdx.x;

    __shared__ float vks[1056];
    __shared__ float qs[128][33];
    __shared__ uint32_t sh[128][17];

    for (int i = tid; i < 1056; i += 128)
        vks[i] = vk[(size_t)head * 1056 + i];

    const float* qbase = qkv + (size_t)b * Nx * NC3 + (size_t)(nch * 128) * NC3 + hh * 32;
#pragma unroll
    for (int i = 0; i < 32; i++) {
        int idx = i * 128 + tid;
        int row = idx >> 5;
        int e = idx & 31;
        qs[row][e] = qbase[(size_t)row * NC3 + e];
    }
    __syncthreads();

    float qr[32];
#pragma unroll
    for (int e = 0; e < 32; e++) qr[e] = qs[tid][e];

    float den = 0.f;
#pragma unroll
    for (int e = 0; e < 32; e++) den += vks[1024 + e] * qr[e];
    float inv = 1.0f / (den + EPSV);

#pragma unroll
    for (int w = 0; w < 16; w++) {
        float s0 = 0.f, s1 = 0.f;
#pragma unroll
        for (int e = 0; e < 32; e++) {
            s0 += vks[(2 * w) * 32 + e] * qr[e];
            s1 += vks[(2 * w + 1) * 32 + e] * qr[e];
        }
        __half2 hp = __halves2half2(__float2half_rn(s0 * inv),
                                    __float2half_rn(s1 * inv));
        sh[tid][w] = *(uint32_t*)&hp;
    }
    __syncthreads();

    const size_t rowbase = (size_t)b * Nx + (size_t)nch * 128;
#pragma unroll
    for (int i = 0; i < 16; i++) {
        int idx = i * 128 + tid;
        int row = idx >> 4;
        int w = idx & 15;
        ath[(rowbase + row) * 512 + hh * 16 + w] = sh[row][w];
    }
}

// ---------------------------------------------------------------------------
extern "C" void kernel_launch(void* const* d_in, const int* in_sizes, int n_in,
                              void* d_out, int out_size)
{
    const float* x     = (const float*)d_in[0];
    const float* Wqkv  = (const float*)d_in[1];
    const float* Wproj = (const float*)d_in[2];
    const float* bproj = (const float*)d_in[3];
    float* out = (float*)d_out;

    float *qkv, *part, *vk;
    uint32_t *xh, *xl, *ath, *wqh, *wph;
    cudaGetSymbolAddress((void**)&qkv,  g_qkv);
    cudaGetSymbolAddress((void**)&part, g_vkpart);
    cudaGetSymbolAddress((void**)&vk,   g_vk);
    cudaGetSymbolAddress((void**)&xh,   g_xh);
    cudaGetSymbolAddress((void**)&xl,   g_xl);
    cudaGetSymbolAddress((void**)&ath,  g_ath);
    cudaGetSymbolAddress((void**)&wqh,  g_wqh);
    cudaGetSymbolAddress((void**)&wph,  g_wph);

    const int M = Bx * Nx;   // 16384

    const int smem2 = 3 * 3 * 10240;   // NCHAIN=2: 92160 B (2 CTAs/SM)
    const int smem1 = 3 * 2 * 10240;   // NCHAIN=1: 61440 B
    cudaFuncSetAttribute(f16_gemm<2, 0>,
                         cudaFuncAttributeMaxDynamicSharedMemorySize, smem2);
    cudaFuncSetAttribute(f16_gemm<1, 0>,
                         cudaFuncAttributeMaxDynamicSharedMemorySize, smem1);
    cudaFuncSetAttribute(f16_gemm<1, 1>,
                         cudaFuncAttributeMaxDynamicSharedMemorySize, smem1);

    // 0) operand prep: x -> hi/lo fp16 planes, weights -> single fp16
    {
        int np;
        np = M * Cx / 2;
        split2_kernel<<<(np + 255) / 256, 256>>>(x, xh, xl, np);
        np = NC3 * Cx / 2;
        round1_kernel<<<(np + 255) / 256, 256>>>(Wqkv, wqh, np);
        np = Cx * Cx / 2;
        round1_kernel<<<(np + 255) / 256, 256>>>(Wproj, wph, np);
    }

    // 1a) q,k = x @ Wqkv[0:2048]^T (2-chain, relu all cols)
    f16_gemm<2, 0><<<dim3(2 * Cx / 128, M / 128), 256, smem2>>>(
        xh, xl, wqh, qkv, nullptr, M, NC3, Cx, 2 * Cx);
    // 1b) v = x @ Wqkv[2048:3072]^T (1-chain, no relu)
    f16_gemm<1, 0><<<dim3(Cx / 128, M / 128), 256, smem1>>>(
        xh, xh, wqh + (size_t)2 * Cx * Cx / 2, qkv + 2 * Cx, nullptr,
        M, NC3, Cx, 0);

    // 2) vk partials + reduce
    vk_partial_kernel<<<1024, 256>>>(qkv, part);
    vk_reduce_kernel<<<(128 * 1056 + 255) / 256, 256>>>(part, vk);

    // 3) attention normalize -> att fp16 plane
    att_kernel<<<4096, 128>>>(qkv, vk, ath);

    // 4) out = att @ Wproj^T + b  (1-chain)
    f16_gemm<1, 1><<<dim3(Cx / 128, M / 128), 256, smem1>>>(
        ath, ath, wph, out, bproj, M, Cx, Cx, 0);
}

// round 10
// speedup vs baseline: 1.6165x; 1.2744x over previous
#include <cuda_runtime.h>
#include <cuda_fp16.h>
#include <cstdint>

#define Bx 4
#define Nx 4096
#define Cx 1024
#define NC3 3072
#define EPSV 1e-15f

// Scratch (device globals — no allocation allowed).  fp16 planes pack 2
// elems per uint32 word, row-major [rows][K/2 words].
__device__ float    g_qkv[(size_t)Bx * Nx * NC3];          // 192 MB fp32
__device__ uint32_t g_xh[(size_t)Bx * Nx * Cx / 2];        // x fp16
__device__ uint32_t g_ath[(size_t)Bx * Nx * Cx / 2];       // att fp16
__device__ uint32_t g_wqh[(size_t)NC3 * Cx / 2];           // Wqkv fp16
__device__ uint32_t g_wph[(size_t)Cx * Cx / 2];            // Wproj fp16
__device__ float    g_vkpart[1024 * 1056];
__device__ float    g_vk[128 * 1056];

__device__ __forceinline__ uint32_t smem_u32(const void* p) {
    uint32_t a;
    asm("{ .reg .u64 t; cvta.to.shared.u64 t, %1; cvt.u32.u64 %0, t; }"
        : "=r"(a) : "l"(p));
    return a;
}
__device__ __forceinline__ void cpa16(uint32_t s, const void* g) {
    asm volatile("cp.async.cg.shared.global [%0], [%1], 16;"
                 :: "r"(s), "l"(g) : "memory");
}
__device__ __forceinline__ void ldsm4(uint32_t& r0, uint32_t& r1,
                                      uint32_t& r2, uint32_t& r3, uint32_t a) {
    asm volatile("ldmatrix.sync.aligned.m8n8.x4.shared.b16 {%0,%1,%2,%3}, [%4];"
                 : "=r"(r0), "=r"(r1), "=r"(r2), "=r"(r3) : "r"(a));
}
__device__ __forceinline__ void mma_f16(float d[4], const uint32_t a[4],
                                        uint32_t b0, uint32_t b1) {
    asm("mma.sync.aligned.m16n8k16.row.col.f32.f16.f16.f32 "
        "{%0,%1,%2,%3}, {%4,%5,%6,%7}, {%8,%9}, {%0,%1,%2,%3};"
        : "+f"(d[0]), "+f"(d[1]), "+f"(d[2]), "+f"(d[3])
        : "r"(a[0]), "r"(a[1]), "r"(a[2]), "r"(a[3]), "r"(b0), "r"(b1));
}

__global__ void round1_kernel(const float* __restrict__ in,
                              uint32_t* __restrict__ oh, int npairs)
{
    int i = blockIdx.x * 256 + threadIdx.x;
    if (i >= npairs) return;
    float2 v = ((const float2*)in)[i];
    __half2 hp = __halves2half2(__float2half_rn(v.x), __float2half_rn(v.y));
    oh[i] = *(uint32_t*)&hp;
}

// ---------------------------------------------------------------------------
// fp16 GEMM:  C[m,n] = sum_k A[m,k]*W[n,k]   (both single-rounded fp16)
// CTA 128x128x32, 8 warps, warp tile 32x64, ldmatrix, 3-stage cp.async,
// 2 CTAs/SM.  MODE 0: relu on n < relu_upto.  MODE 1: add bias[n].
// ---------------------------------------------------------------------------
template <int MODE>
__global__ __launch_bounds__(256, 2) void f16_gemm(
    const uint32_t* __restrict__ Ah_, const uint32_t* __restrict__ Wh_,
    float* __restrict__ C, const float* __restrict__ bias,
    int M, int Nn, int K, int relu_upto)
{
    constexpr int PITCH = 80;
    constexpr int A_TILE = 128 * PITCH;              // 10240
    constexpr int OFF_B  = A_TILE;
    constexpr int STAGE  = 2 * A_TILE;               // 20480
    extern __shared__ char smem[];
    const uint32_t sb = smem_u32(smem);

    const int tid = threadIdx.x;
    const int wid = tid >> 5;
    const int lane = tid & 31;
    const int g = lane >> 2;
    const int tig = lane & 3;
    const int warp_m = (wid & 3) * 32;
    const int warp_n = (wid >> 2) * 64;
    const int m0 = blockIdx.y * 128;
    const int n0 = blockIdx.x * 128;

    const __half* Ah = (const __half*)Ah_;
    const __half* Wh = (const __half*)Wh_;

    float acc[2][8][4];
#pragma unroll
    for (int mt = 0; mt < 2; mt++)
#pragma unroll
        for (int nt = 0; nt < 8; nt++)
#pragma unroll
            for (int j = 0; j < 4; j++) acc[mt][nt][j] = 0.0f;

    const int NK = K / 32;
    const int crow = tid >> 2;                       // 0..63
    const int cchk = tid & 3;                        // 16B chunk (8 halfs)

    auto issue = [&](int it, int s) {
        const int kt = it * 32 + cchk * 8;
        const uint32_t st = sb + (uint32_t)s * STAGE;
#pragma unroll
        for (int i = 0; i < 2; i++) {
            int r = crow + i * 64;
            uint32_t so = (uint32_t)(r * PITCH + cchk * 16);
            cpa16(st + so, Ah + (size_t)(m0 + r) * K + kt);
            cpa16(st + OFF_B + so, Wh + (size_t)(n0 + r) * K + kt);
        }
        asm volatile("cp.async.commit_group;" ::: "memory");
    };

    issue(0, 0);
    if (NK > 1) issue(1, 1);

    const uint32_t lrow = (uint32_t)(lane & 15);
    const uint32_t lchk = (uint32_t)(lane >> 4) * 16;

    for (int it = 0; it < NK; it++) {
        if (it + 1 < NK) {
            asm volatile("cp.async.wait_group 1;" ::: "memory");
        } else {
            asm volatile("cp.async.wait_group 0;" ::: "memory");
        }
        __syncthreads();
        if (it + 2 < NK) issue(it + 2, (it + 2) % 3);

        const uint32_t st = sb + (uint32_t)(it % 3) * STAGE;
        const uint32_t abase = st + (uint32_t)(warp_m + lrow) * PITCH + lchk;
        const uint32_t bbase = st + OFF_B + (uint32_t)(warp_n + lrow) * PITCH + lchk;

#pragma unroll
        for (int kk = 0; kk < 2; kk++) {
            uint32_t ah[2][4];
#pragma unroll
            for (int mt = 0; mt < 2; mt++) {
                uint32_t ao = abase + (uint32_t)(mt * 16 * PITCH + kk * 32);
                ldsm4(ah[mt][0], ah[mt][1], ah[mt][2], ah[mt][3], ao);
            }
            uint32_t b[8][2];
#pragma unroll
            for (int p = 0; p < 4; p++) {
                uint32_t bo = bbase + (uint32_t)(p * 16 * PITCH + kk * 32);
                uint32_t r0, r1, r2, r3;
                ldsm4(r0, r1, r2, r3, bo);
                b[2 * p][0] = r0; b[2 * p][1] = r2;
                b[2 * p + 1][0] = r1; b[2 * p + 1][1] = r3;
            }
#pragma unroll
            for (int nt = 0; nt < 8; nt++)
#pragma unroll
                for (int mt = 0; mt < 2; mt++)
                    mma_f16(acc[mt][nt], ah[mt], b[nt][0], b[nt][1]);
        }
    }

    // epilogue (fp32 out)
#pragma unroll
    for (int mt = 0; mt < 2; mt++) {
        int mA = m0 + warp_m + mt * 16 + g;
#pragma unroll
        for (int nt = 0; nt < 8; nt++) {
            int n = n0 + warp_n + nt * 8 + 2 * tig;
            float e0 = acc[mt][nt][0], e1 = acc[mt][nt][1];
            float e2 = acc[mt][nt][2], e3 = acc[mt][nt][3];
            if (MODE == 0) {
                if (n < relu_upto)     { e0 = fmaxf(e0, 0.f); e2 = fmaxf(e2, 0.f); }
                if (n + 1 < relu_upto) { e1 = fmaxf(e1, 0.f); e3 = fmaxf(e3, 0.f); }
            } else {
                float bb0 = bias[n], bb1 = bias[n + 1];
                e0 += bb0; e1 += bb1; e2 += bb0; e3 += bb1;
            }
            *(float2*)(C + (size_t)mA * Nn + n)       = make_float2(e0, e1);
            *(float2*)(C + (size_t)(mA + 8) * Nn + n) = make_float2(e2, e3);
        }
    }
}

// ---------------------------------------------------------------------------
// vk partial reduction (unchanged)
// ---------------------------------------------------------------------------
__global__ __launch_bounds__(256) void vk_partial_kernel(
    const float* __restrict__ qkv, float* __restrict__ part)
{
    const int blk = blockIdx.x;
    const int slice = blk & 7;
    const int head = blk >> 3;
    const int b = head >> 5;
    const int hh = head & 31;
    const int tid = threadIdx.x;

    __shared__ float ks[8][32];
    __shared__ float vs[8][32];

    float acc[5] = {0.f, 0.f, 0.f, 0.f, 0.f};

    const float* base = qkv + (size_t)b * Nx * NC3 + (size_t)(slice * 512) * NC3 + hh * 32;
    const int r = tid >> 5;
    const int e = tid & 31;

    for (int n0 = 0; n0 < 512; n0 += 8) {
        const float* p = base + (size_t)(n0 + r) * NC3 + e;
        float kreg = p[1024];
        float vreg = p[2048];
        __syncthreads();
        ks[r][e] = kreg;
        vs[r][e] = vreg;
        __syncthreads();
#pragma unroll
        for (int rr = 0; rr < 8; rr++) {
#pragma unroll
            for (int i = 0; i < 5; i++) {
                int idx = tid + 256 * i;
                if (idx < 1056) {
                    int d = idx >> 5;
                    int ee = idx & 31;
                    float vval = (d == 32) ? 1.0f : vs[rr][d];
                    acc[i] += vval * ks[rr][ee];
                }
            }
        }
    }
#pragma unroll
    for (int i = 0; i < 5; i++) {
        int idx = tid + 256 * i;
        if (idx < 1056) part[(size_t)blk * 1056 + idx] = acc[i];
    }
}

__global__ void vk_reduce_kernel(const float* __restrict__ part,
                                 float* __restrict__ vk)
{
    int idx = blockIdx.x * 256 + threadIdx.x;
    if (idx >= 128 * 1056) return;
    int head = idx / 1056;
    int j = idx % 1056;
    float s = 0.f;
#pragma unroll
    for (int sl = 0; sl < 8; sl++)
        s += part[(size_t)(head * 8 + sl) * 1056 + j];
    vk[idx] = s;
}

// ---------------------------------------------------------------------------
// att kernel: normalize, write single fp16 plane (GEMM2 A operand)
// ---------------------------------------------------------------------------
__global__ __launch_bounds__(128) void att_kernel(
    const float* __restrict__ qkv, const float* __restrict__ vk,
    uint32_t* __restrict__ ath)
{
    const int blk = blockIdx.x;
    const int nch = blk & 31;
    const int head = blk >> 5;
    const int b = head >> 5;
    const int hh = head & 31;
    const int tid = threadIdx.x;

    __shared__ float vks[1056];
    __shared__ float qs[128][33];
    __shared__ uint32_t sh[128][17];

    for (int i = tid; i < 1056; i += 128)
        vks[i] = vk[(size_t)head * 1056 + i];

    const float* qbase = qkv + (size_t)b * Nx * NC3 + (size_t)(nch * 128) * NC3 + hh * 32;
#pragma unroll
    for (int i = 0; i < 32; i++) {
        int idx = i * 128 + tid;
        int row = idx >> 5;
        int e = idx & 31;
        qs[row][e] = qbase[(size_t)row * NC3 + e];
    }
    __syncthreads();

    float qr[32];
#pragma unroll
    for (int e = 0; e < 32; e++) qr[e] = qs[tid][e];

    float den = 0.f;
#pragma unroll
    for (int e = 0; e < 32; e++) den += vks[1024 + e] * qr[e];
    float inv = 1.0f / (den + EPSV);

#pragma unroll
    for (int w = 0; w < 16; w++) {
        float s0 = 0.f, s1 = 0.f;
#pragma unroll
        for (int e = 0; e < 32; e++) {
            s0 += vks[(2 * w) * 32 + e] * qr[e];
            s1 += vks[(2 * w + 1) * 32 + e] * qr[e];
        }
        __half2 hp = __halves2half2(__float2half_rn(s0 * inv),
                                    __float2half_rn(s1 * inv));
        sh[tid][w] = *(uint32_t*)&hp;
    }
    __syncthreads();

    const size_t rowbase = (size_t)b * Nx + (size_t)nch * 128;
#pragma unroll
    for (int i = 0; i < 16; i++) {
        int idx = i * 128 + tid;
        int row = idx >> 4;
        int w = idx & 15;
        ath[(rowbase + row) * 512 + hh * 16 + w] = sh[row][w];
    }
}

// ---------------------------------------------------------------------------
extern "C" void kernel_launch(void* const* d_in, const int* in_sizes, int n_in,
                              void* d_out, int out_size)
{
    const float* x     = (const float*)d_in[0];
    const float* Wqkv  = (const float*)d_in[1];
    const float* Wproj = (const float*)d_in[2];
    const float* bproj = (const float*)d_in[3];
    float* out = (float*)d_out;

    float *qkv, *part, *vk;
    uint32_t *xh, *ath, *wqh, *wph;
    cudaGetSymbolAddress((void**)&qkv,  g_qkv);
    cudaGetSymbolAddress((void**)&part, g_vkpart);
    cudaGetSymbolAddress((void**)&vk,   g_vk);
    cudaGetSymbolAddress((void**)&xh,   g_xh);
    cudaGetSymbolAddress((void**)&ath,  g_ath);
    cudaGetSymbolAddress((void**)&wqh,  g_wqh);
    cudaGetSymbolAddress((void**)&wph,  g_wph);

    const int M = Bx * Nx;   // 16384

    const int smem = 3 * 2 * 10240;   // 61440 B per CTA (2 CTAs/SM)
    cudaFuncSetAttribute(f16_gemm<0>,
                         cudaFuncAttributeMaxDynamicSharedMemorySize, smem);
    cudaFuncSetAttribute(f16_gemm<1>,
                         cudaFuncAttributeMaxDynamicSharedMemorySize, smem);

    // 0) operand prep: round everything to fp16 once
    {
        int np;
        np = M * Cx / 2;
        round1_kernel<<<(np + 255) / 256, 256>>>(x, xh, np);
        np = NC3 * Cx / 2;
        round1_kernel<<<(np + 255) / 256, 256>>>(Wqkv, wqh, np);
        np = Cx * Cx / 2;
        round1_kernel<<<(np + 255) / 256, 256>>>(Wproj, wph, np);
    }

    // 1) qkv = x @ Wqkv^T (single fp16 chain), relu on n < 2048
    f16_gemm<0><<<dim3(NC3 / 128, M / 128), 256, smem>>>(
        xh, wqh, qkv, nullptr, M, NC3, Cx, 2 * Cx);

    // 2) vk partials + reduce
    vk_partial_kernel<<<1024, 256>>>(qkv, part);
    vk_reduce_kernel<<<(128 * 1056 + 255) / 256, 256>>>(part, vk);

    // 3) attention normalize -> att fp16 plane
    att_kernel<<<4096, 128>>>(qkv, vk, ath);

    // 4) out = att @ Wproj^T + b  (single fp16 chain)
    f16_gemm<1><<<dim3(Cx / 128, M / 128), 256, smem>>>(
        ath, wph, out, bproj, M, Cx, Cx, 0);
}

// round 11
// speedup vs baseline: 1.8023x; 1.1149x over previous
#include <cuda_runtime.h>
#include <cuda_fp16.h>
#include <cstdint>

#define Bx 4
#define Nx 4096
#define Cx 1024
#define NC3 3072
#define EPSV 1e-15f

// Scratch (device globals — no allocation allowed)
__device__ __half   g_qkvh[(size_t)Bx * Nx * NC3];         // 96 MB fp16 qkv
__device__ uint32_t g_xh[(size_t)Bx * Nx * Cx / 2];        // x fp16
__device__ uint32_t g_ath[(size_t)Bx * Nx * Cx / 2];       // att fp16
__device__ uint32_t g_wqh[(size_t)NC3 * Cx / 2];           // Wqkv fp16
__device__ uint32_t g_wph[(size_t)Cx * Cx / 2];            // Wproj fp16
__device__ float    g_vkpart[1024 * 1056];
__device__ float    g_vk[128 * 1056];

__device__ __forceinline__ uint32_t smem_u32(const void* p) {
    uint32_t a;
    asm("{ .reg .u64 t; cvta.to.shared.u64 t, %1; cvt.u32.u64 %0, t; }"
        : "=r"(a) : "l"(p));
    return a;
}
__device__ __forceinline__ void cpa16(uint32_t s, const void* g) {
    asm volatile("cp.async.cg.shared.global [%0], [%1], 16;"
                 :: "r"(s), "l"(g) : "memory");
}
__device__ __forceinline__ void ldsm4(uint32_t& r0, uint32_t& r1,
                                      uint32_t& r2, uint32_t& r3, uint32_t a) {
    asm volatile("ldmatrix.sync.aligned.m8n8.x4.shared.b16 {%0,%1,%2,%3}, [%4];"
                 : "=r"(r0), "=r"(r1), "=r"(r2), "=r"(r3) : "r"(a));
}
__device__ __forceinline__ void mma_f16(float d[4], const uint32_t a[4],
                                        uint32_t b0, uint32_t b1) {
    asm("mma.sync.aligned.m16n8k16.row.col.f32.f16.f16.f32 "
        "{%0,%1,%2,%3}, {%4,%5,%6,%7}, {%8,%9}, {%0,%1,%2,%3};"
        : "+f"(d[0]), "+f"(d[1]), "+f"(d[2]), "+f"(d[3])
        : "r"(a[0]), "r"(a[1]), "r"(a[2]), "r"(a[3]), "r"(b0), "r"(b1));
}

__global__ void round1_kernel(const float* __restrict__ in,
                              uint32_t* __restrict__ oh, int npairs)
{
    int i = blockIdx.x * 256 + threadIdx.x;
    if (i >= npairs) return;
    float2 v = ((const float2*)in)[i];
    __half2 hp = __halves2half2(__float2half_rn(v.x), __float2half_rn(v.y));
    oh[i] = *(uint32_t*)&hp;
}

// ---------------------------------------------------------------------------
// fp16 GEMM:  C[m,n] = sum_k A[m,k]*W[n,k]   (both single-rounded fp16)
// CTA 128x128x32, 8 warps, warp tile 32x64, ldmatrix, 3-stage cp.async,
// 2 CTAs/SM.  MODE 0: relu on n<relu_upto, OUTPUT fp16.  MODE 1: +bias, fp32.
// ---------------------------------------------------------------------------
template <int MODE>
__global__ __launch_bounds__(256, 2) void f16_gemm(
    const uint32_t* __restrict__ Ah_, const uint32_t* __restrict__ Wh_,
    void* __restrict__ Cv, const float* __restrict__ bias,
    int M, int Nn, int K, int relu_upto)
{
    constexpr int PITCH = 80;
    constexpr int A_TILE = 128 * PITCH;              // 10240
    constexpr int OFF_B  = A_TILE;
    constexpr int STAGE  = 2 * A_TILE;               // 20480
    extern __shared__ char smem[];
    const uint32_t sb = smem_u32(smem);

    const int tid = threadIdx.x;
    const int wid = tid >> 5;
    const int lane = tid & 31;
    const int g = lane >> 2;
    const int tig = lane & 3;
    const int warp_m = (wid & 3) * 32;
    const int warp_n = (wid >> 2) * 64;
    const int m0 = blockIdx.y * 128;
    const int n0 = blockIdx.x * 128;

    const __half* Ah = (const __half*)Ah_;
    const __half* Wh = (const __half*)Wh_;

    float acc[2][8][4];
#pragma unroll
    for (int mt = 0; mt < 2; mt++)
#pragma unroll
        for (int nt = 0; nt < 8; nt++)
#pragma unroll
            for (int j = 0; j < 4; j++) acc[mt][nt][j] = 0.0f;

    const int NK = K / 32;
    const int crow = tid >> 2;                       // 0..63
    const int cchk = tid & 3;                        // 16B chunk (8 halfs)

    auto issue = [&](int it, int s) {
        const int kt = it * 32 + cchk * 8;
        const uint32_t st = sb + (uint32_t)s * STAGE;
#pragma unroll
        for (int i = 0; i < 2; i++) {
            int r = crow + i * 64;
            uint32_t so = (uint32_t)(r * PITCH + cchk * 16);
            cpa16(st + so, Ah + (size_t)(m0 + r) * K + kt);
            cpa16(st + OFF_B + so, Wh + (size_t)(n0 + r) * K + kt);
        }
        asm volatile("cp.async.commit_group;" ::: "memory");
    };

    issue(0, 0);
    if (NK > 1) issue(1, 1);

    const uint32_t lrow = (uint32_t)(lane & 15);
    const uint32_t lchk = (uint32_t)(lane >> 4) * 16;

    for (int it = 0; it < NK; it++) {
        if (it + 1 < NK) {
            asm volatile("cp.async.wait_group 1;" ::: "memory");
        } else {
            asm volatile("cp.async.wait_group 0;" ::: "memory");
        }
        __syncthreads();
        if (it + 2 < NK) issue(it + 2, (it + 2) % 3);

        const uint32_t st = sb + (uint32_t)(it % 3) * STAGE;
        const uint32_t abase = st + (uint32_t)(warp_m + lrow) * PITCH + lchk;
        const uint32_t bbase = st + OFF_B + (uint32_t)(warp_n + lrow) * PITCH + lchk;

#pragma unroll
        for (int kk = 0; kk < 2; kk++) {
            uint32_t ah[2][4];
#pragma unroll
            for (int mt = 0; mt < 2; mt++) {
                uint32_t ao = abase + (uint32_t)(mt * 16 * PITCH + kk * 32);
                ldsm4(ah[mt][0], ah[mt][1], ah[mt][2], ah[mt][3], ao);
            }
            uint32_t b[8][2];
#pragma unroll
            for (int p = 0; p < 4; p++) {
                uint32_t bo = bbase + (uint32_t)(p * 16 * PITCH + kk * 32);
                uint32_t r0, r1, r2, r3;
                ldsm4(r0, r1, r2, r3, bo);
                b[2 * p][0] = r0; b[2 * p][1] = r2;
                b[2 * p + 1][0] = r1; b[2 * p + 1][1] = r3;
            }
#pragma unroll
            for (int nt = 0; nt < 8; nt++)
#pragma unroll
                for (int mt = 0; mt < 2; mt++)
                    mma_f16(acc[mt][nt], ah[mt], b[nt][0], b[nt][1]);
        }
    }

    // epilogue
#pragma unroll
    for (int mt = 0; mt < 2; mt++) {
        int mA = m0 + warp_m + mt * 16 + g;
#pragma unroll
        for (int nt = 0; nt < 8; nt++) {
            int n = n0 + warp_n + nt * 8 + 2 * tig;
            float e0 = acc[mt][nt][0], e1 = acc[mt][nt][1];
            float e2 = acc[mt][nt][2], e3 = acc[mt][nt][3];
            if (MODE == 0) {
                if (n < relu_upto)     { e0 = fmaxf(e0, 0.f); e2 = fmaxf(e2, 0.f); }
                if (n + 1 < relu_upto) { e1 = fmaxf(e1, 0.f); e3 = fmaxf(e3, 0.f); }
                __half* Ch = (__half*)Cv;
                __half2 h01 = __halves2half2(__float2half_rn(e0), __float2half_rn(e1));
                __half2 h23 = __halves2half2(__float2half_rn(e2), __float2half_rn(e3));
                *(uint32_t*)(Ch + (size_t)mA * Nn + n)       = *(uint32_t*)&h01;
                *(uint32_t*)(Ch + (size_t)(mA + 8) * Nn + n) = *(uint32_t*)&h23;
            } else {
                float* Cf = (float*)Cv;
                float bb0 = bias[n], bb1 = bias[n + 1];
                e0 += bb0; e1 += bb1; e2 += bb0; e3 += bb1;
                *(float2*)(Cf + (size_t)mA * Nn + n)       = make_float2(e0, e1);
                *(float2*)(Cf + (size_t)(mA + 8) * Nn + n) = make_float2(e2, e3);
            }
        }
    }
}

// ---------------------------------------------------------------------------
// vk partial: block = (head, slice of 512 n).  256 thr = 16 dg x 16 ep.
// Thread owns (d = 2dg, 2dg+1) x (e = 2ep, 2ep+1); dg==0 also sums k (d=32).
// fp16 global loads staged to fp32 smem; 2 LDS.64 + 4 FMA per n per thread.
// ---------------------------------------------------------------------------
__global__ __launch_bounds__(256) void vk_partial_kernel(
    const __half* __restrict__ qkvh, float* __restrict__ part)
{
    const int blk = blockIdx.x;
    const int slice = blk & 7;
    const int head = blk >> 3;
    const int b = head >> 5;
    const int hh = head & 31;
    const int tid = threadIdx.x;
    const int ep = tid & 15;
    const int dg = tid >> 4;

    __shared__ float ks[32][34];
    __shared__ float vs[32][34];

    float a00 = 0.f, a01 = 0.f, a10 = 0.f, a11 = 0.f, s0 = 0.f, s1 = 0.f;
    const size_t tokbase = (size_t)b * Nx + (size_t)slice * 512;

    for (int nc = 0; nc < 16; nc++) {
        __syncthreads();
#pragma unroll
        for (int j = 0; j < 4; j++) {
            int idx = tid + j * 256;
            int kv = idx >> 9;
            int r = (idx >> 4) & 31;
            int c = idx & 15;
            const __half* p = qkvh + (tokbase + nc * 32 + r) * NC3
                              + (kv ? 2048 : 1024) + hh * 32 + 2 * c;
            float2 f = __half22float2(*(const __half2*)p);
            float* dst = kv ? &vs[r][2 * c] : &ks[r][2 * c];
            dst[0] = f.x; dst[1] = f.y;
        }
        __syncthreads();
#pragma unroll
        for (int rr = 0; rr < 32; rr++) {
            float2 k2 = *(const float2*)&ks[rr][2 * ep];
            float2 v2 = *(const float2*)&vs[rr][2 * dg];
            a00 += v2.x * k2.x; a01 += v2.x * k2.y;
            a10 += v2.y * k2.x; a11 += v2.y * k2.y;
            if (dg == 0) { s0 += k2.x; s1 += k2.y; }
        }
    }

    float* pb = part + (size_t)blk * 1056;
    pb[(2 * dg) * 32 + 2 * ep]           = a00;
    pb[(2 * dg) * 32 + 2 * ep + 1]       = a01;
    pb[(2 * dg + 1) * 32 + 2 * ep]       = a10;
    pb[(2 * dg + 1) * 32 + 2 * ep + 1]   = a11;
    if (dg == 0) {
        pb[1024 + 2 * ep]     = s0;
        pb[1024 + 2 * ep + 1] = s1;
    }
}

__global__ void vk_reduce_kernel(const float* __restrict__ part,
                                 float* __restrict__ vk)
{
    int idx = blockIdx.x * 256 + threadIdx.x;
    if (idx >= 128 * 1056) return;
    int head = idx / 1056;
    int j = idx % 1056;
    float s = 0.f;
#pragma unroll
    for (int sl = 0; sl < 8; sl++)
        s += part[(size_t)(head * 8 + sl) * 1056 + j];
    vk[idx] = s;
}

// ---------------------------------------------------------------------------
// att via mma.sync: per (head, 128-token chunk): C[128n, 40d] = q @ vkh^T,
// K=32.  den = col d=32; ratio in epilogue; writes ath fp16.
// 128 threads = 4 warps, each warp 32 n-rows (2 m-tiles) x 5 n-tiles.
// ---------------------------------------------------------------------------
__global__ __launch_bounds__(128) void att_kernel(
    const __half* __restrict__ qkvh, const float* __restrict__ vk,
    uint32_t* __restrict__ ath)
{
    const int blk = blockIdx.x;
    const int nch = blk & 31;
    const int head = blk >> 5;
    const int b = head >> 5;
    const int hh = head & 31;
    const int tid = threadIdx.x;
    const int wid = tid >> 5;
    const int lane = tid & 31;

    __shared__ __half qs[128][40];     // 80 B pitch
    __shared__ __half vkh[48][40];

    const size_t rowbase = (size_t)b * Nx + (size_t)nch * 128;

    // stage q (fp16, 16 words per thread)
#pragma unroll
    for (int i = 0; i < 16; i++) {
        int idx = i * 128 + tid;
        int row = idx >> 4;
        int c = idx & 15;
        uint32_t w = *(const uint32_t*)(qkvh + (rowbase + row) * NC3 + hh * 32 + 2 * c);
        *(uint32_t*)&qs[row][2 * c] = w;
    }
    // stage vk -> fp16, zero-pad rows 33..47
    for (int idx = tid; idx < 48 * 32; idx += 128) {
        int d = idx >> 5;
        int e = idx & 31;
        float v = (d < 33) ? vk[(size_t)head * 1056 + d * 32 + e] : 0.f;
        vkh[d][e] = __float2half_rn(v);
    }
    __syncthreads();

    const uint32_t lrow = (uint32_t)(lane & 15);
    const uint32_t lchk = (uint32_t)(lane >> 4) * 16;
    const uint32_t qsb = smem_u32(qs);
    const uint32_t vkb = smem_u32(vkh);

    uint32_t a[2][2][4];
#pragma unroll
    for (int mt = 0; mt < 2; mt++)
#pragma unroll
        for (int kk = 0; kk < 2; kk++) {
            uint32_t ao = qsb + (uint32_t)((wid * 32 + mt * 16 + lrow) * 80) + lchk + kk * 32;
            ldsm4(a[mt][kk][0], a[mt][kk][1], a[mt][kk][2], a[mt][kk][3], ao);
        }
    uint32_t bfr[6][2][2];
#pragma unroll
    for (int p = 0; p < 3; p++)
#pragma unroll
        for (int kk = 0; kk < 2; kk++) {
            uint32_t bo = vkb + (uint32_t)((p * 16 + lrow) * 80) + lchk + kk * 32;
            uint32_t r0, r1, r2, r3;
            ldsm4(r0, r1, r2, r3, bo);
            bfr[2 * p][kk][0] = r0;     bfr[2 * p][kk][1] = r2;
            bfr[2 * p + 1][kk][0] = r1; bfr[2 * p + 1][kk][1] = r3;
        }

    float c[2][5][4];
#pragma unroll
    for (int mt = 0; mt < 2; mt++)
#pragma unroll
        for (int nt = 0; nt < 5; nt++) {
#pragma unroll
            for (int j = 0; j < 4; j++) c[mt][nt][j] = 0.f;
#pragma unroll
            for (int kk = 0; kk < 2; kk++)
                mma_f16(c[mt][nt], a[mt][kk], bfr[nt][kk][0], bfr[nt][kk][1]);
        }

    // epilogue: normalize by den (col d=32 = nt4, col0 of tig==0 lanes)
    const int g = lane >> 2;
    const int tig = lane & 3;
#pragma unroll
    for (int mt = 0; mt < 2; mt++) {
        float d0 = __shfl_sync(0xffffffffu, c[mt][4][0], lane & 28);
        float d1 = __shfl_sync(0xffffffffu, c[mt][4][2], lane & 28);
        float i0 = 1.0f / (d0 + EPSV);
        float i1 = 1.0f / (d1 + EPSV);
        size_t t0 = rowbase + (size_t)(wid * 32 + mt * 16 + g);
#pragma unroll
        for (int nt = 0; nt < 4; nt++) {
            __half2 h0 = __halves2half2(__float2half_rn(c[mt][nt][0] * i0),
                                        __float2half_rn(c[mt][nt][1] * i0));
            __half2 h1 = __halves2half2(__float2half_rn(c[mt][nt][2] * i1),
                                        __float2half_rn(c[mt][nt][3] * i1));
            ath[t0 * 512 + hh * 16 + nt * 4 + tig]       = *(uint32_t*)&h0;
            ath[(t0 + 8) * 512 + hh * 16 + nt * 4 + tig] = *(uint32_t*)&h1;
        }
    }
}

// ---------------------------------------------------------------------------
extern "C" void kernel_launch(void* const* d_in, const int* in_sizes, int n_in,
                              void* d_out, int out_size)
{
    const float* x     = (const float*)d_in[0];
    const float* Wqkv  = (const float*)d_in[1];
    const float* Wproj = (const float*)d_in[2];
    const float* bproj = (const float*)d_in[3];
    float* out = (float*)d_out;

    __half* qkvh;
    float *part, *vk;
    uint32_t *xh, *ath, *wqh, *wph;
    cudaGetSymbolAddress((void**)&qkvh, g_qkvh);
    cudaGetSymbolAddress((void**)&part, g_vkpart);
    cudaGetSymbolAddress((void**)&vk,   g_vk);
    cudaGetSymbolAddress((void**)&xh,   g_xh);
    cudaGetSymbolAddress((void**)&ath,  g_ath);
    cudaGetSymbolAddress((void**)&wqh,  g_wqh);
    cudaGetSymbolAddress((void**)&wph,  g_wph);

    const int M = Bx * Nx;   // 16384

    const int smem = 3 * 2 * 10240;   // 61440 B per CTA (2 CTAs/SM)
    cudaFuncSetAttribute(f16_gemm<0>,
                         cudaFuncAttributeMaxDynamicSharedMemorySize, smem);
    cudaFuncSetAttribute(f16_gemm<1>,
                         cudaFuncAttributeMaxDynamicSharedMemorySize, smem);

    // 0) operand prep: round inputs/weights to fp16 once
    {
        int np;
        np = M * Cx / 2;
        round1_kernel<<<(np + 255) / 256, 256>>>(x, xh, np);
        np = NC3 * Cx / 2;
        round1_kernel<<<(np + 255) / 256, 256>>>(Wqkv, wqh, np);
        np = Cx * Cx / 2;
        round1_kernel<<<(np + 255) / 256, 256>>>(Wproj, wph, np);
    }

    // 1) qkv = x @ Wqkv^T -> fp16 (relu fused on n < 2048)
    f16_gemm<0><<<dim3(NC3 / 128, M / 128), 256, smem>>>(
        xh, wqh, qkvh, nullptr, M, NC3, Cx, 2 * Cx);

    // 2) vk partials + reduce
    vk_partial_kernel<<<1024, 256>>>(qkvh, part);
    vk_reduce_kernel<<<(128 * 1056 + 255) / 256, 256>>>(part, vk);

    // 3) attention normalize via tensor cores -> ath fp16
    att_kernel<<<4096, 128>>>(qkvh, vk, ath);

    // 4) out = att @ Wproj^T + b  (fp32 out)
    f16_gemm<1><<<dim3(Cx / 128, M / 128), 256, smem>>>(
        ath, wph, out, bproj, M, Cx, Cx, 0);
}

// round 12
// speedup vs baseline: 1.9476x; 1.0806x over previous
#include <cuda_runtime.h>
#include <cuda_fp16.h>
#include <cstdint>

#define Bx 4
#define Nx 4096
#define Cx 1024
#define NC3 3072
#define EPSV 1e-15f

// Scratch (device globals — no allocation allowed)
__device__ __half   g_qkvh[(size_t)Bx * Nx * NC3];         // 96 MB fp16 qkv
__device__ uint32_t g_xh[(size_t)Bx * Nx * Cx / 2];        // x fp16
__device__ uint32_t g_ath[(size_t)Bx * Nx * Cx / 2];       // att fp16
__device__ uint32_t g_wqh[(size_t)NC3 * Cx / 2];           // Wqkv fp16
__device__ uint32_t g_wph[(size_t)Cx * Cx / 2];            // Wproj fp16
__device__ __half   g_vkh[128 * 1536];                     // vk fp16 [head][48*32]

__device__ __forceinline__ uint32_t smem_u32(const void* p) {
    uint32_t a;
    asm("{ .reg .u64 t; cvta.to.shared.u64 t, %1; cvt.u32.u64 %0, t; }"
        : "=r"(a) : "l"(p));
    return a;
}
__device__ __forceinline__ void cpa16(uint32_t s, const void* g) {
    asm volatile("cp.async.cg.shared.global [%0], [%1], 16;"
                 :: "r"(s), "l"(g) : "memory");
}
__device__ __forceinline__ void ldsm4(uint32_t& r0, uint32_t& r1,
                                      uint32_t& r2, uint32_t& r3, uint32_t a) {
    asm volatile("ldmatrix.sync.aligned.m8n8.x4.shared.b16 {%0,%1,%2,%3}, [%4];"
                 : "=r"(r0), "=r"(r1), "=r"(r2), "=r"(r3) : "r"(a));
}
__device__ __forceinline__ void ldsm4t(uint32_t& r0, uint32_t& r1,
                                       uint32_t& r2, uint32_t& r3, uint32_t a) {
    asm volatile("ldmatrix.sync.aligned.m8n8.x4.trans.shared.b16 {%0,%1,%2,%3}, [%4];"
                 : "=r"(r0), "=r"(r1), "=r"(r2), "=r"(r3) : "r"(a));
}
__device__ __forceinline__ void mma_f16(float d[4], const uint32_t a[4],
                                        uint32_t b0, uint32_t b1) {
    asm("mma.sync.aligned.m16n8k16.row.col.f32.f16.f16.f32 "
        "{%0,%1,%2,%3}, {%4,%5,%6,%7}, {%8,%9}, {%0,%1,%2,%3};"
        : "+f"(d[0]), "+f"(d[1]), "+f"(d[2]), "+f"(d[3])
        : "r"(a[0]), "r"(a[1]), "r"(a[2]), "r"(a[3]), "r"(b0), "r"(b1));
}

__global__ void round1_kernel(const float* __restrict__ in,
                              uint32_t* __restrict__ oh, int npairs)
{
    int i = blockIdx.x * 256 + threadIdx.x;
    if (i >= npairs) return;
    float2 v = ((const float2*)in)[i];
    __half2 hp = __halves2half2(__float2half_rn(v.x), __float2half_rn(v.y));
    oh[i] = *(uint32_t*)&hp;
}

// ---------------------------------------------------------------------------
// fp16 GEMM:  C[m,n] = sum_k A[m,k]*W[n,k]   (both single-rounded fp16)
// CTA 128x128x32, 8 warps, warp tile 32x64, ldmatrix, 3-stage cp.async,
// 2 CTAs/SM.  MODE 0: relu on n<relu_upto, OUTPUT fp16.  MODE 1: +bias, fp32.
// ---------------------------------------------------------------------------
template <int MODE>
__global__ __launch_bounds__(256, 2) void f16_gemm(
    const uint32_t* __restrict__ Ah_, const uint32_t* __restrict__ Wh_,
    void* __restrict__ Cv, const float* __restrict__ bias,
    int M, int Nn, int K, int relu_upto)
{
    constexpr int PITCH = 80;
    constexpr int A_TILE = 128 * PITCH;              // 10240
    constexpr int OFF_B  = A_TILE;
    constexpr int STAGE  = 2 * A_TILE;               // 20480
    extern __shared__ char smem[];
    const uint32_t sb = smem_u32(smem);

    const int tid = threadIdx.x;
    const int wid = tid >> 5;
    const int lane = tid & 31;
    const int g = lane >> 2;
    const int tig = lane & 3;
    const int warp_m = (wid & 3) * 32;
    const int warp_n = (wid >> 2) * 64;
    const int m0 = blockIdx.y * 128;
    const int n0 = blockIdx.x * 128;

    const __half* Ah = (const __half*)Ah_;
    const __half* Wh = (const __half*)Wh_;

    float acc[2][8][4];
#pragma unroll
    for (int mt = 0; mt < 2; mt++)
#pragma unroll
        for (int nt = 0; nt < 8; nt++)
#pragma unroll
            for (int j = 0; j < 4; j++) acc[mt][nt][j] = 0.0f;

    const int NK = K / 32;
    const int crow = tid >> 2;
    const int cchk = tid & 3;

    auto issue = [&](int it, int s) {
        const int kt = it * 32 + cchk * 8;
        const uint32_t st = sb + (uint32_t)s * STAGE;
#pragma unroll
        for (int i = 0; i < 2; i++) {
            int r = crow + i * 64;
            uint32_t so = (uint32_t)(r * PITCH + cchk * 16);
            cpa16(st + so, Ah + (size_t)(m0 + r) * K + kt);
            cpa16(st + OFF_B + so, Wh + (size_t)(n0 + r) * K + kt);
        }
        asm volatile("cp.async.commit_group;" ::: "memory");
    };

    issue(0, 0);
    if (NK > 1) issue(1, 1);

    const uint32_t lrow = (uint32_t)(lane & 15);
    const uint32_t lchk = (uint32_t)(lane >> 4) * 16;

    for (int it = 0; it < NK; it++) {
        if (it + 1 < NK) {
            asm volatile("cp.async.wait_group 1;" ::: "memory");
        } else {
            asm volatile("cp.async.wait_group 0;" ::: "memory");
        }
        __syncthreads();
        if (it + 2 < NK) issue(it + 2, (it + 2) % 3);

        const uint32_t st = sb + (uint32_t)(it % 3) * STAGE;
        const uint32_t abase = st + (uint32_t)(warp_m + lrow) * PITCH + lchk;
        const uint32_t bbase = st + OFF_B + (uint32_t)(warp_n + lrow) * PITCH + lchk;

#pragma unroll
        for (int kk = 0; kk < 2; kk++) {
            uint32_t ah[2][4];
#pragma unroll
            for (int mt = 0; mt < 2; mt++) {
                uint32_t ao = abase + (uint32_t)(mt * 16 * PITCH + kk * 32);
                ldsm4(ah[mt][0], ah[mt][1], ah[mt][2], ah[mt][3], ao);
            }
            uint32_t b[8][2];
#pragma unroll
            for (int p = 0; p < 4; p++) {
                uint32_t bo = bbase + (uint32_t)(p * 16 * PITCH + kk * 32);
                uint32_t r0, r1, r2, r3;
                ldsm4(r0, r1, r2, r3, bo);
                b[2 * p][0] = r0; b[2 * p][1] = r2;
                b[2 * p + 1][0] = r1; b[2 * p + 1][1] = r3;
            }
#pragma unroll
            for (int nt = 0; nt < 8; nt++)
#pragma unroll
                for (int mt = 0; mt < 2; mt++)
                    mma_f16(acc[mt][nt], ah[mt], b[nt][0], b[nt][1]);
        }
    }

    // epilogue
#pragma unroll
    for (int mt = 0; mt < 2; mt++) {
        int mA = m0 + warp_m + mt * 16 + g;
#pragma unroll
        for (int nt = 0; nt < 8; nt++) {
            int n = n0 + warp_n + nt * 8 + 2 * tig;
            float e0 = acc[mt][nt][0], e1 = acc[mt][nt][1];
            float e2 = acc[mt][nt][2], e3 = acc[mt][nt][3];
            if (MODE == 0) {
                if (n < relu_upto)     { e0 = fmaxf(e0, 0.f); e2 = fmaxf(e2, 0.f); }
                if (n + 1 < relu_upto) { e1 = fmaxf(e1, 0.f); e3 = fmaxf(e3, 0.f); }
                __half* Ch = (__half*)Cv;
                __half2 h01 = __halves2half2(__float2half_rn(e0), __float2half_rn(e1));
                __half2 h23 = __halves2half2(__float2half_rn(e2), __float2half_rn(e3));
                *(uint32_t*)(Ch + (size_t)mA * Nn + n)       = *(uint32_t*)&h01;
                *(uint32_t*)(Ch + (size_t)(mA + 8) * Nn + n) = *(uint32_t*)&h23;
            } else {
                float* Cf = (float*)Cv;
                float bb0 = bias[n], bb1 = bias[n + 1];
                e0 += bb0; e1 += bb1; e2 += bb0; e3 += bb1;
                *(float2*)(Cf + (size_t)mA * Nn + n)       = make_float2(e0, e1);
                *(float2*)(Cf + (size_t)(mA + 8) * Nn + n) = make_float2(e2, e3);
            }
        }
    }
}

// ---------------------------------------------------------------------------
// vk via tensor cores.  One CTA per head (grid 128, 128 threads = 4 warps).
// vk[d,e] = sum_n v[n,d]*k[n,e]; row d=32 = sum_n k[n,e] via ones-fragment.
// Warp w split-K over tokens; ldmatrix.trans from [token][channel] tiles.
// Output fp16 [48][32] per head (rows 33..47 zero).
// ---------------------------------------------------------------------------
__global__ __launch_bounds__(128) void vk_mma_kernel(
    const __half* __restrict__ qkvh, __half* __restrict__ vkh_out)
{
    // dynamic smem: 2 stages x (ks[128][40] + vs[128][40]) halfs = 40960 B
    constexpr int STAGEH = 2 * 128 * 40;             // halfs per stage
    extern __shared__ char smraw[];
    __half* smh = (__half*)smraw;
    const uint32_t sbase = smem_u32(smraw);

    const int head = blockIdx.x;
    const int b = head >> 5;
    const int hh = head & 31;
    const int tid = threadIdx.x;
    const int wid = tid >> 5;
    const int lane = tid & 31;
    const int grp = lane >> 3;
    const int lr = lane & 7;

    float acc[3][4][4];
#pragma unroll
    for (int mt = 0; mt < 3; mt++)
#pragma unroll
        for (int nt = 0; nt < 4; nt++)
#pragma unroll
            for (int j = 0; j < 4; j++) acc[mt][nt][j] = 0.f;

    // ones fragment for m-tile 2 (row 0 of tile = global d=32)
    const uint32_t ones = (lane < 4) ? 0x3C003C00u : 0u;
    const uint32_t aden[4] = {ones, 0u, ones, 0u};

    auto stage = [&](int it, int s) {
        const size_t tokbase = (size_t)b * Nx + (size_t)it * 128;
#pragma unroll
        for (int j = 0; j < 8; j++) {
            int idx = tid + j * 128;
            int kv = idx >> 9;                       // 0=k, 1=v
            int r = (idx >> 2) & 127;
            int c = idx & 3;
            const __half* gp = qkvh + (tokbase + r) * NC3
                               + (kv ? 2048 : 1024) + hh * 32 + c * 8;
            uint32_t dst = sbase + (uint32_t)(s * STAGEH + kv * 5120
                                              + r * 40 + c * 8) * 2;
            cpa16(dst, gp);
        }
        asm volatile("cp.async.commit_group;" ::: "memory");
    };

    stage(0, 0);

    for (int it = 0; it < 32; it++) {
        if (it + 1 < 32) {
            stage(it + 1, (it + 1) & 1);
            asm volatile("cp.async.wait_group 1;" ::: "memory");
        } else {
            asm volatile("cp.async.wait_group 0;" ::: "memory");
        }
        __syncthreads();

        const int s = it & 1;
        const uint32_t ks0 = sbase + (uint32_t)(s * STAGEH) * 2;
        const uint32_t vs0 = ks0 + 5120 * 2;

#pragma unroll
        for (int step = 0; step < 2; step++) {
            const int tok0 = wid * 32 + step * 16;
            // A (v^T): m-tiles 0,1.  group g -> (row +(g>>1)*8, col (g&1)*8)
            uint32_t av[2][4];
#pragma unroll
            for (int mt = 0; mt < 2; mt++) {
                uint32_t ao = vs0 + (uint32_t)((tok0 + (grp >> 1) * 8 + lr) * 40
                                               + mt * 16 + (grp & 1) * 8) * 2;
                ldsm4t(av[mt][0], av[mt][1], av[mt][2], av[mt][3], ao);
            }
            // B (k^T): group g -> (row +(g&1)*8, col (g>>1)*8); two loads e0-15, e16-31
            uint32_t bk[4][2];
#pragma unroll
            for (int half = 0; half < 2; half++) {
                uint32_t bo = ks0 + (uint32_t)((tok0 + (grp & 1) * 8 + lr) * 40
                                               + half * 16 + (grp >> 1) * 8) * 2;
                uint32_t r0, r1, r2, r3;
                ldsm4t(r0, r1, r2, r3, bo);
                bk[2 * half][0] = r0;     bk[2 * half][1] = r1;
                bk[2 * half + 1][0] = r2; bk[2 * half + 1][1] = r3;
            }
#pragma unroll
            for (int nt = 0; nt < 4; nt++) {
#pragma unroll
                for (int mt = 0; mt < 2; mt++)
                    mma_f16(acc[mt][nt], av[mt], bk[nt][0], bk[nt][1]);
                mma_f16(acc[2][nt], aden, bk[nt][0], bk[nt][1]);
            }
        }
        __syncthreads();
    }

    // cross-warp reduce (reuse smem as float [4][48][33])
    float* red = (float*)smraw;
    const int g4 = lane >> 2;
    const int tig = lane & 3;
#pragma unroll
    for (int mt = 0; mt < 3; mt++)
#pragma unroll
        for (int nt = 0; nt < 4; nt++) {
            int m = mt * 16 + g4;
            int e = nt * 8 + 2 * tig;
            float* rb = red + (size_t)wid * 1584;
            rb[m * 33 + e]           = acc[mt][nt][0];
            rb[m * 33 + e + 1]       = acc[mt][nt][1];
            rb[(m + 8) * 33 + e]     = acc[mt][nt][2];
            rb[(m + 8) * 33 + e + 1] = acc[mt][nt][3];
        }
    __syncthreads();

#pragma unroll
    for (int i = 0; i < 12; i++) {
        int idx = tid + i * 128;                     // 0..1535
        int m = idx >> 5;
        int e = idx & 31;
        float s = red[m * 33 + e] + red[1584 + m * 33 + e]
                + red[2 * 1584 + m * 33 + e] + red[3 * 1584 + m * 33 + e];
        vkh_out[(size_t)head * 1536 + idx] = __float2half_rn(s);
    }
}

// ---------------------------------------------------------------------------
// att via mma.sync: per (head, 128-token chunk): C[128n, 40d] = q @ vkh^T,
// K=32.  den = col d=32; ratio in epilogue; writes ath fp16.
// ---------------------------------------------------------------------------
__global__ __launch_bounds__(128) void att_kernel(
    const __half* __restrict__ qkvh, const __half* __restrict__ vkh_g,
    uint32_t* __restrict__ ath)
{
    const int blk = blockIdx.x;
    const int nch = blk & 31;
    const int head = blk >> 5;
    const int b = head >> 5;
    const int hh = head & 31;
    const int tid = threadIdx.x;
    const int wid = tid >> 5;
    const int lane = tid & 31;

    __shared__ __half qs[128][40];
    __shared__ __half vkh[48][40];

    const size_t rowbase = (size_t)b * Nx + (size_t)nch * 128;

#pragma unroll
    for (int i = 0; i < 16; i++) {
        int idx = i * 128 + tid;
        int row = idx >> 4;
        int c = idx & 15;
        uint32_t w = *(const uint32_t*)(qkvh + (rowbase + row) * NC3 + hh * 32 + 2 * c);
        *(uint32_t*)&qs[row][2 * c] = w;
    }
    // load fp16 vk tile directly (48 rows x 32, 16 words/row)
#pragma unroll
    for (int i = 0; i < 6; i++) {
        int idx = i * 128 + tid;                     // 0..767
        int d = idx >> 4;
        int c = idx & 15;
        uint32_t w = ((const uint32_t*)(vkh_g + (size_t)head * 1536))[idx];
        *(uint32_t*)&vkh[d][2 * c] = w;
    }
    __syncthreads();

    const uint32_t lrow = (uint32_t)(lane & 15);
    const uint32_t lchk = (uint32_t)(lane >> 4) * 16;
    const uint32_t qsb = smem_u32(qs);
    const uint32_t vkb = smem_u32(vkh);

    uint32_t a[2][2][4];
#pragma unroll
    for (int mt = 0; mt < 2; mt++)
#pragma unroll
        for (int kk = 0; kk < 2; kk++) {
            uint32_t ao = qsb + (uint32_t)((wid * 32 + mt * 16 + lrow) * 80) + lchk + kk * 32;
            ldsm4(a[mt][kk][0], a[mt][kk][1], a[mt][kk][2], a[mt][kk][3], ao);
        }
    uint32_t bfr[6][2][2];
#pragma unroll
    for (int p = 0; p < 3; p++)
#pragma unroll
        for (int kk = 0; kk < 2; kk++) {
            uint32_t bo = vkb + (uint32_t)((p * 16 + lrow) * 80) + lchk + kk * 32;
            uint32_t r0, r1, r2, r3;
            ldsm4(r0, r1, r2, r3, bo);
            bfr[2 * p][kk][0] = r0;     bfr[2 * p][kk][1] = r2;
            bfr[2 * p + 1][kk][0] = r1; bfr[2 * p + 1][kk][1] = r3;
        }

    float c[2][5][4];
#pragma unroll
    for (int mt = 0; mt < 2; mt++)
#pragma unroll
        for (int nt = 0; nt < 5; nt++) {
#pragma unroll
            for (int j = 0; j < 4; j++) c[mt][nt][j] = 0.f;
#pragma unroll
            for (int kk = 0; kk < 2; kk++)
                mma_f16(c[mt][nt], a[mt][kk], bfr[nt][kk][0], bfr[nt][kk][1]);
        }

    const int g = lane >> 2;
    const int tig = lane & 3;
#pragma unroll
    for (int mt = 0; mt < 2; mt++) {
        float d0 = __shfl_sync(0xffffffffu, c[mt][4][0], lane & 28);
        float d1 = __shfl_sync(0xffffffffu, c[mt][4][2], lane & 28);
        float i0 = 1.0f / (d0 + EPSV);
        float i1 = 1.0f / (d1 + EPSV);
        size_t t0 = rowbase + (size_t)(wid * 32 + mt * 16 + g);
#pragma unroll
        for (int nt = 0; nt < 4; nt++) {
            __half2 h0 = __halves2half2(__float2half_rn(c[mt][nt][0] * i0),
                                        __float2half_rn(c[mt][nt][1] * i0));
            __half2 h1 = __halves2half2(__float2half_rn(c[mt][nt][2] * i1),
                                        __float2half_rn(c[mt][nt][3] * i1));
            ath[t0 * 512 + hh * 16 + nt * 4 + tig]       = *(uint32_t*)&h0;
            ath[(t0 + 8) * 512 + hh * 16 + nt * 4 + tig] = *(uint32_t*)&h1;
        }
    }
}

// ---------------------------------------------------------------------------
extern "C" void kernel_launch(void* const* d_in, const int* in_sizes, int n_in,
                              void* d_out, int out_size)
{
    const float* x     = (const float*)d_in[0];
    const float* Wqkv  = (const float*)d_in[1];
    const float* Wproj = (const float*)d_in[2];
    const float* bproj = (const float*)d_in[3];
    float* out = (float*)d_out;

    __half *qkvh, *vkh;
    uint32_t *xh, *ath, *wqh, *wph;
    cudaGetSymbolAddress((void**)&qkvh, g_qkvh);
    cudaGetSymbolAddress((void**)&vkh,  g_vkh);
    cudaGetSymbolAddress((void**)&xh,   g_xh);
    cudaGetSymbolAddress((void**)&ath,  g_ath);
    cudaGetSymbolAddress((void**)&wqh,  g_wqh);
    cudaGetSymbolAddress((void**)&wph,  g_wph);

    const int M = Bx * Nx;   // 16384

    const int smem = 3 * 2 * 10240;   // 61440 B per CTA (2 CTAs/SM)
    cudaFuncSetAttribute(f16_gemm<0>,
                         cudaFuncAttributeMaxDynamicSharedMemorySize, smem);
    cudaFuncSetAttribute(f16_gemm<1>,
                         cudaFuncAttributeMaxDynamicSharedMemorySize, smem);

    // 0) operand prep: round inputs/weights to fp16 once
    {
        int np;
        np = M * Cx / 2;
        round1_kernel<<<(np + 255) / 256, 256>>>(x, xh, np);
        np = NC3 * Cx / 2;
        round1_kernel<<<(np + 255) / 256, 256>>>(Wqkv, wqh, np);
        np = Cx * Cx / 2;
        round1_kernel<<<(np + 255) / 256, 256>>>(Wproj, wph, np);
    }

    // 1) qkv = x @ Wqkv^T -> fp16 (relu fused on n < 2048)
    f16_gemm<0><<<dim3(NC3 / 128, M / 128), 256, smem>>>(
        xh, wqh, qkvh, nullptr, M, NC3, Cx, 2 * Cx);

    // 2) vk via tensor cores -> fp16 [head][48x32]
    vk_mma_kernel<<<128, 128, 40960>>>(qkvh, vkh);

    // 3) attention normalize via tensor cores -> ath fp16
    att_kernel<<<4096, 128>>>(qkvh, vkh, ath);

    // 4) out = att @ Wproj^T + b  (fp32 out)
    f16_gemm<1><<<dim3(Cx / 128, M / 128), 256, smem>>>(
        ath, wph, out, bproj, M, Cx, Cx, 0);
}

// round 13
// speedup vs baseline: 1.9501x; 1.0013x over previous
#include <cuda_runtime.h>
#include <cuda_fp16.h>
#include <cstdint>

#define Bx 4
#define Nx 4096
#define Cx 1024
#define NC3 3072
#define EPSV 1e-15f

// Scratch (device globals — no allocation allowed)
__device__ __half   g_qkvh[(size_t)Bx * Nx * NC3];         // 96 MB fp16 qkv
__device__ uint32_t g_xh[(size_t)Bx * Nx * Cx / 2];        // x fp16
__device__ uint32_t g_ath[(size_t)Bx * Nx * Cx / 2];       // att fp16
__device__ uint32_t g_wqh[(size_t)NC3 * Cx / 2];           // Wqkv fp16
__device__ uint32_t g_wph[(size_t)Cx * Cx / 2];            // Wproj fp16
__device__ __half   g_vkh[128 * 1536];                     // vk fp16 [head][48*32]

__device__ __forceinline__ uint32_t smem_u32(const void* p) {
    uint32_t a;
    asm("{ .reg .u64 t; cvta.to.shared.u64 t, %1; cvt.u32.u64 %0, t; }"
        : "=r"(a) : "l"(p));
    return a;
}
__device__ __forceinline__ void cpa16(uint32_t s, const void* g) {
    asm volatile("cp.async.cg.shared.global [%0], [%1], 16;"
                 :: "r"(s), "l"(g) : "memory");
}
__device__ __forceinline__ void ldsm4(uint32_t& r0, uint32_t& r1,
                                      uint32_t& r2, uint32_t& r3, uint32_t a) {
    asm volatile("ldmatrix.sync.aligned.m8n8.x4.shared.b16 {%0,%1,%2,%3}, [%4];"
                 : "=r"(r0), "=r"(r1), "=r"(r2), "=r"(r3) : "r"(a));
}
__device__ __forceinline__ void ldsm4t(uint32_t& r0, uint32_t& r1,
                                       uint32_t& r2, uint32_t& r3, uint32_t a) {
    asm volatile("ldmatrix.sync.aligned.m8n8.x4.trans.shared.b16 {%0,%1,%2,%3}, [%4];"
                 : "=r"(r0), "=r"(r1), "=r"(r2), "=r"(r3) : "r"(a));
}
__device__ __forceinline__ void mma_f16(float d[4], const uint32_t a[4],
                                        uint32_t b0, uint32_t b1) {
    asm("mma.sync.aligned.m16n8k16.row.col.f32.f16.f16.f32 "
        "{%0,%1,%2,%3}, {%4,%5,%6,%7}, {%8,%9}, {%0,%1,%2,%3};"
        : "+f"(d[0]), "+f"(d[1]), "+f"(d[2]), "+f"(d[3])
        : "r"(a[0]), "r"(a[1]), "r"(a[2]), "r"(a[3]), "r"(b0), "r"(b1));
}

// fused operand prep: three fp32->fp16 segments in one launch
__global__ void prep_kernel(const float* __restrict__ x,  uint32_t* __restrict__ xh,  int npx,
                            const float* __restrict__ wq, uint32_t* __restrict__ wqh, int npq,
                            const float* __restrict__ wp, uint32_t* __restrict__ wph, int npp)
{
    int i = blockIdx.x * 256 + threadIdx.x;
    const float* in;
    uint32_t* out;
    int j;
    if (i < npx)                  { in = x;  out = xh;  j = i; }
    else if (i < npx + npq)       { in = wq; out = wqh; j = i - npx; }
    else if (i < npx + npq + npp) { in = wp; out = wph; j = i - npx - npq; }
    else return;
    float2 v = ((const float2*)in)[j];
    __half2 hp = __halves2half2(__float2half_rn(v.x), __float2half_rn(v.y));
    out[j] = *(uint32_t*)&hp;
}

// ---------------------------------------------------------------------------
// fp16 GEMM:  C[m,n] = sum_k A[m,k]*W[n,k]   (both single-rounded fp16)
// CTA 128xBN x32, 8 warps (4m x 2n), warp tile 32 x BN/2, ldmatrix,
// 3-stage cp.async, 2 CTAs/SM.
// MODE 0: relu on n<relu_upto, OUTPUT fp16.  MODE 1: +bias, fp32 out.
// ---------------------------------------------------------------------------
template <int BN, int MODE>
__global__ __launch_bounds__(256, 2) void f16_gemm(
    const uint32_t* __restrict__ Ah_, const uint32_t* __restrict__ Wh_,
    void* __restrict__ Cv, const float* __restrict__ bias,
    int M, int Nn, int K, int relu_upto)
{
    constexpr int PITCH = 80;
    constexpr int A_TILE = 128 * PITCH;
    constexpr int B_TILE = BN * PITCH;
    constexpr int OFF_B  = A_TILE;
    constexpr int STAGE  = A_TILE + B_TILE;
    constexpr int NT = BN / 16;                      // 8-col n-tiles per warp
    constexpr int NP = BN / 32;                      // b ldsm4 count per kk
    extern __shared__ char smem[];
    const uint32_t sb = smem_u32(smem);

    const int tid = threadIdx.x;
    const int wid = tid >> 5;
    const int lane = tid & 31;
    const int g = lane >> 2;
    const int tig = lane & 3;
    const int warp_m = (wid & 3) * 32;
    const int warp_n = (wid >> 2) * (BN / 2);
    const int m0 = blockIdx.y * 128;
    const int n0 = blockIdx.x * BN;

    const __half* Ah = (const __half*)Ah_;
    const __half* Wh = (const __half*)Wh_;

    float acc[2][NT][4];
#pragma unroll
    for (int mt = 0; mt < 2; mt++)
#pragma unroll
        for (int nt = 0; nt < NT; nt++)
#pragma unroll
            for (int j = 0; j < 4; j++) acc[mt][nt][j] = 0.0f;

    const int NK = K / 32;
    const int crow = tid >> 2;
    const int cchk = tid & 3;

    auto issue = [&](int it, int s) {
        const int kt = it * 32 + cchk * 8;
        const uint32_t st = sb + (uint32_t)s * STAGE;
#pragma unroll
        for (int i = 0; i < 2; i++) {
            int r = crow + i * 64;
            uint32_t so = (uint32_t)(r * PITCH + cchk * 16);
            cpa16(st + so, Ah + (size_t)(m0 + r) * K + kt);
            if (r < BN)
                cpa16(st + OFF_B + so, Wh + (size_t)(n0 + r) * K + kt);
        }
        asm volatile("cp.async.commit_group;" ::: "memory");
    };

    issue(0, 0);
    if (NK > 1) issue(1, 1);

    const uint32_t lrow = (uint32_t)(lane & 15);
    const uint32_t lchk = (uint32_t)(lane >> 4) * 16;

    for (int it = 0; it < NK; it++) {
        if (it + 1 < NK) {
            asm volatile("cp.async.wait_group 1;" ::: "memory");
        } else {
            asm volatile("cp.async.wait_group 0;" ::: "memory");
        }
        __syncthreads();
        if (it + 2 < NK) issue(it + 2, (it + 2) % 3);

        const uint32_t st = sb + (uint32_t)(it % 3) * STAGE;
        const uint32_t abase = st + (uint32_t)(warp_m + lrow) * PITCH + lchk;
        const uint32_t bbase = st + OFF_B + (uint32_t)(warp_n + lrow) * PITCH + lchk;

#pragma unroll
        for (int kk = 0; kk < 2; kk++) {
            uint32_t ah[2][4];
#pragma unroll
            for (int mt = 0; mt < 2; mt++) {
                uint32_t ao = abase + (uint32_t)(mt * 16 * PITCH + kk * 32);
                ldsm4(ah[mt][0], ah[mt][1], ah[mt][2], ah[mt][3], ao);
            }
            uint32_t b[NT][2];
#pragma unroll
            for (int p = 0; p < NP; p++) {
                uint32_t bo = bbase + (uint32_t)(p * 16 * PITCH + kk * 32);
                uint32_t r0, r1, r2, r3;
                ldsm4(r0, r1, r2, r3, bo);
                b[2 * p][0] = r0; b[2 * p][1] = r2;
                b[2 * p + 1][0] = r1; b[2 * p + 1][1] = r3;
            }
#pragma unroll
            for (int nt = 0; nt < NT; nt++)
#pragma unroll
                for (int mt = 0; mt < 2; mt++)
                    mma_f16(acc[mt][nt], ah[mt], b[nt][0], b[nt][1]);
        }
    }

    // epilogue
#pragma unroll
    for (int mt = 0; mt < 2; mt++) {
        int mA = m0 + warp_m + mt * 16 + g;
#pragma unroll
        for (int nt = 0; nt < NT; nt++) {
            int n = n0 + warp_n + nt * 8 + 2 * tig;
            float e0 = acc[mt][nt][0], e1 = acc[mt][nt][1];
            float e2 = acc[mt][nt][2], e3 = acc[mt][nt][3];
            if (MODE == 0) {
                if (n < relu_upto)     { e0 = fmaxf(e0, 0.f); e2 = fmaxf(e2, 0.f); }
                if (n + 1 < relu_upto) { e1 = fmaxf(e1, 0.f); e3 = fmaxf(e3, 0.f); }
                __half* Ch = (__half*)Cv;
                __half2 h01 = __halves2half2(__float2half_rn(e0), __float2half_rn(e1));
                __half2 h23 = __halves2half2(__float2half_rn(e2), __float2half_rn(e3));
                *(uint32_t*)(Ch + (size_t)mA * Nn + n)       = *(uint32_t*)&h01;
                *(uint32_t*)(Ch + (size_t)(mA + 8) * Nn + n) = *(uint32_t*)&h23;
            } else {
                float* Cf = (float*)Cv;
                float bb0 = bias[n], bb1 = bias[n + 1];
                e0 += bb0; e1 += bb1; e2 += bb0; e3 += bb1;
                *(float2*)(Cf + (size_t)mA * Nn + n)       = make_float2(e0, e1);
                *(float2*)(Cf + (size_t)(mA + 8) * Nn + n) = make_float2(e2, e3);
            }
        }
    }
}

// ---------------------------------------------------------------------------
// vk via tensor cores (unchanged from R12).
// ---------------------------------------------------------------------------
__global__ __launch_bounds__(128) void vk_mma_kernel(
    const __half* __restrict__ qkvh, __half* __restrict__ vkh_out)
{
    constexpr int STAGEH = 2 * 128 * 40;
    extern __shared__ char smraw[];
    const uint32_t sbase = smem_u32(smraw);

    const int head = blockIdx.x;
    const int b = head >> 5;
    const int hh = head & 31;
    const int tid = threadIdx.x;
    const int wid = tid >> 5;
    const int lane = tid & 31;
    const int grp = lane >> 3;
    const int lr = lane & 7;

    float acc[3][4][4];
#pragma unroll
    for (int mt = 0; mt < 3; mt++)
#pragma unroll
        for (int nt = 0; nt < 4; nt++)
#pragma unroll
            for (int j = 0; j < 4; j++) acc[mt][nt][j] = 0.f;

    const uint32_t ones = (lane < 4) ? 0x3C003C00u : 0u;
    const uint32_t aden[4] = {ones, 0u, ones, 0u};

    auto stage = [&](int it, int s) {
        const size_t tokbase = (size_t)b * Nx + (size_t)it * 128;
#pragma unroll
        for (int j = 0; j < 8; j++) {
            int idx = tid + j * 128;
            int kv = idx >> 9;
            int r = (idx >> 2) & 127;
            int c = idx & 3;
            const __half* gp = qkvh + (tokbase + r) * NC3
                               + (kv ? 2048 : 1024) + hh * 32 + c * 8;
            uint32_t dst = sbase + (uint32_t)(s * STAGEH + kv * 5120
                                              + r * 40 + c * 8) * 2;
            cpa16(dst, gp);
        }
        asm volatile("cp.async.commit_group;" ::: "memory");
    };

    stage(0, 0);

    for (int it = 0; it < 32; it++) {
        if (it + 1 < 32) {
            stage(it + 1, (it + 1) & 1);
            asm volatile("cp.async.wait_group 1;" ::: "memory");
        } else {
            asm volatile("cp.async.wait_group 0;" ::: "memory");
        }
        __syncthreads();

        const int s = it & 1;
        const uint32_t ks0 = sbase + (uint32_t)(s * STAGEH) * 2;
        const uint32_t vs0 = ks0 + 5120 * 2;

#pragma unroll
        for (int step = 0; step < 2; step++) {
            const int tok0 = wid * 32 + step * 16;
            uint32_t av[2][4];
#pragma unroll
            for (int mt = 0; mt < 2; mt++) {
                uint32_t ao = vs0 + (uint32_t)((tok0 + (grp >> 1) * 8 + lr) * 40
                                               + mt * 16 + (grp & 1) * 8) * 2;
                ldsm4t(av[mt][0], av[mt][1], av[mt][2], av[mt][3], ao);
            }
            uint32_t bk[4][2];
#pragma unroll
            for (int half = 0; half < 2; half++) {
                uint32_t bo = ks0 + (uint32_t)((tok0 + (grp & 1) * 8 + lr) * 40
                                               + half * 16 + (grp >> 1) * 8) * 2;
                uint32_t r0, r1, r2, r3;
                ldsm4t(r0, r1, r2, r3, bo);
                bk[2 * half][0] = r0;     bk[2 * half][1] = r1;
                bk[2 * half + 1][0] = r2; bk[2 * half + 1][1] = r3;
            }
#pragma unroll
            for (int nt = 0; nt < 4; nt++) {
#pragma unroll
                for (int mt = 0; mt < 2; mt++)
                    mma_f16(acc[mt][nt], av[mt], bk[nt][0], bk[nt][1]);
                mma_f16(acc[2][nt], aden, bk[nt][0], bk[nt][1]);
            }
        }
        __syncthreads();
    }

    float* red = (float*)smraw;
    const int g4 = lane >> 2;
    const int tig = lane & 3;
#pragma unroll
    for (int mt = 0; mt < 3; mt++)
#pragma unroll
        for (int nt = 0; nt < 4; nt++) {
            int m = mt * 16 + g4;
            int e = nt * 8 + 2 * tig;
            float* rb = red + (size_t)wid * 1584;
            rb[m * 33 + e]           = acc[mt][nt][0];
            rb[m * 33 + e + 1]       = acc[mt][nt][1];
            rb[(m + 8) * 33 + e]     = acc[mt][nt][2];
            rb[(m + 8) * 33 + e + 1] = acc[mt][nt][3];
        }
    __syncthreads();

#pragma unroll
    for (int i = 0; i < 12; i++) {
        int idx = tid + i * 128;
        int m = idx >> 5;
        int e = idx & 31;
        float s = red[m * 33 + e] + red[1584 + m * 33 + e]
                + red[2 * 1584 + m * 33 + e] + red[3 * 1584 + m * 33 + e];
        vkh_out[(size_t)head * 1536 + idx] = __float2half_rn(s);
    }
}

// ---------------------------------------------------------------------------
// att via mma.sync (unchanged from R12).
// ---------------------------------------------------------------------------
__global__ __launch_bounds__(128) void att_kernel(
    const __half* __restrict__ qkvh, const __half* __restrict__ vkh_g,
    uint32_t* __restrict__ ath)
{
    const int blk = blockIdx.x;
    const int nch = blk & 31;
    const int head = blk >> 5;
    const int b = head >> 5;
    const int hh = head & 31;
    const int tid = threadIdx.x;
    const int wid = tid >> 5;
    const int lane = tid & 31;

    __shared__ __half qs[128][40];
    __shared__ __half vkh[48][40];

    const size_t rowbase = (size_t)b * Nx + (size_t)nch * 128;

#pragma unroll
    for (int i = 0; i < 16; i++) {
        int idx = i * 128 + tid;
        int row = idx >> 4;
        int c = idx & 15;
        uint32_t w = *(const uint32_t*)(qkvh + (rowbase + row) * NC3 + hh * 32 + 2 * c);
        *(uint32_t*)&qs[row][2 * c] = w;
    }
#pragma unroll
    for (int i = 0; i < 6; i++) {
        int idx = i * 128 + tid;
        int d = idx >> 4;
        int c = idx & 15;
        uint32_t w = ((const uint32_t*)(vkh_g + (size_t)head * 1536))[idx];
        *(uint32_t*)&vkh[d][2 * c] = w;
    }
    __syncthreads();

    const uint32_t lrow = (uint32_t)(lane & 15);
    const uint32_t lchk = (uint32_t)(lane >> 4) * 16;
    const uint32_t qsb = smem_u32(qs);
    const uint32_t vkb = smem_u32(vkh);

    uint32_t a[2][2][4];
#pragma unroll
    for (int mt = 0; mt < 2; mt++)
#pragma unroll
        for (int kk = 0; kk < 2; kk++) {
            uint32_t ao = qsb + (uint32_t)((wid * 32 + mt * 16 + lrow) * 80) + lchk + kk * 32;
            ldsm4(a[mt][kk][0], a[mt][kk][1], a[mt][kk][2], a[mt][kk][3], ao);
        }
    uint32_t bfr[6][2][2];
#pragma unroll
    for (int p = 0; p < 3; p++)
#pragma unroll
        for (int kk = 0; kk < 2; kk++) {
            uint32_t bo = vkb + (uint32_t)((p * 16 + lrow) * 80) + lchk + kk * 32;
            uint32_t r0, r1, r2, r3;
            ldsm4(r0, r1, r2, r3, bo);
            bfr[2 * p][kk][0] = r0;     bfr[2 * p][kk][1] = r2;
            bfr[2 * p + 1][kk][0] = r1; bfr[2 * p + 1][kk][1] = r3;
        }

    float c[2][5][4];
#pragma unroll
    for (int mt = 0; mt < 2; mt++)
#pragma unroll
        for (int nt = 0; nt < 5; nt++) {
#pragma unroll
            for (int j = 0; j < 4; j++) c[mt][nt][j] = 0.f;
#pragma unroll
            for (int kk = 0; kk < 2; kk++)
                mma_f16(c[mt][nt], a[mt][kk], bfr[nt][kk][0], bfr[nt][kk][1]);
        }

    const int g = lane >> 2;
    const int tig = lane & 3;
#pragma unroll
    for (int mt = 0; mt < 2; mt++) {
        float d0 = __shfl_sync(0xffffffffu, c[mt][4][0], lane & 28);
        float d1 = __shfl_sync(0xffffffffu, c[mt][4][2], lane & 28);
        float i0 = 1.0f / (d0 + EPSV);
        float i1 = 1.0f / (d1 + EPSV);
        size_t t0 = rowbase + (size_t)(wid * 32 + mt * 16 + g);
#pragma unroll
        for (int nt = 0; nt < 4; nt++) {
            __half2 h0 = __halves2half2(__float2half_rn(c[mt][nt][0] * i0),
                                        __float2half_rn(c[mt][nt][1] * i0));
            __half2 h1 = __halves2half2(__float2half_rn(c[mt][nt][2] * i1),
                                        __float2half_rn(c[mt][nt][3] * i1));
            ath[t0 * 512 + hh * 16 + nt * 4 + tig]       = *(uint32_t*)&h0;
            ath[(t0 + 8) * 512 + hh * 16 + nt * 4 + tig] = *(uint32_t*)&h1;
        }
    }
}

// ---------------------------------------------------------------------------
extern "C" void kernel_launch(void* const* d_in, const int* in_sizes, int n_in,
                              void* d_out, int out_size)
{
    const float* x     = (const float*)d_in[0];
    const float* Wqkv  = (const float*)d_in[1];
    const float* Wproj = (const float*)d_in[2];
    const float* bproj = (const float*)d_in[3];
    float* out = (float*)d_out;

    __half *qkvh, *vkh;
    uint32_t *xh, *ath, *wqh, *wph;
    cudaGetSymbolAddress((void**)&qkvh, g_qkvh);
    cudaGetSymbolAddress((void**)&vkh,  g_vkh);
    cudaGetSymbolAddress((void**)&xh,   g_xh);
    cudaGetSymbolAddress((void**)&ath,  g_ath);
    cudaGetSymbolAddress((void**)&wqh,  g_wqh);
    cudaGetSymbolAddress((void**)&wph,  g_wph);

    const int M = Bx * Nx;   // 16384

    const int smem1 = 3 * (128 + 96) * 80;   // BN=96: 53760 B
    const int smem2 = 3 * (128 + 64) * 80;   // BN=64: 46080 B
    cudaFuncSetAttribute(f16_gemm<96, 0>,
                         cudaFuncAttributeMaxDynamicSharedMemorySize, smem1);
    cudaFuncSetAttribute(f16_gemm<64, 1>,
                         cudaFuncAttributeMaxDynamicSharedMemorySize, smem2);

    // 0) fused operand prep (fp32 -> fp16)
    {
        int npx = M * Cx / 2;
        int npq = NC3 * Cx / 2;
        int npp = Cx * Cx / 2;
        int tot = npx + npq + npp;
        prep_kernel<<<(tot + 255) / 256, 256>>>(x, xh, npx, Wqkv, wqh, npq,
                                                Wproj, wph, npp);
    }

    // 1) qkv = x @ Wqkv^T -> fp16 (relu fused on n < 2048), BN=96
    f16_gemm<96, 0><<<dim3(NC3 / 96, M / 128), 256, smem1>>>(
        xh, wqh, qkvh, nullptr, M, NC3, Cx, 2 * Cx);

    // 2) vk via tensor cores -> fp16 [head][48x32]
    vk_mma_kernel<<<128, 128, 40960>>>(qkvh, vkh);

    // 3) attention normalize via tensor cores -> ath fp16
    att_kernel<<<4096, 128>>>(qkvh, vkh, ath);

    // 4) out = att @ Wproj^T + b  (fp32 out), BN=64
    f16_gemm<64, 1><<<dim3(Cx / 64, M / 128), 256, smem2>>>(
        ath, wph, out, bproj, M, Cx, Cx, 0);
}

// round 14
// speedup vs baseline: 1.9746x; 1.0126x over previous
#include <cuda_runtime.h>
#include <cuda_fp16.h>
#include <cstdint>

#define Bx 4
#define Nx 4096
#define Cx 1024
#define NC3 3072
#define EPSV 1e-15f

// Scratch (device globals — no allocation allowed)
__device__ __half   g_qkvh[(size_t)Bx * Nx * NC3];         // 96 MB fp16 qkv
__device__ uint32_t g_xh[(size_t)Bx * Nx * Cx / 2];        // x fp16
__device__ uint32_t g_ath[(size_t)Bx * Nx * Cx / 2];       // att fp16
__device__ uint32_t g_wqh[(size_t)NC3 * Cx / 2];           // Wqkv fp16
__device__ uint32_t g_wph[(size_t)Cx * Cx / 2];            // Wproj fp16
__device__ float    g_vkp[256 * 1536];                     // vk fp32 partials

__device__ __forceinline__ uint32_t smem_u32(const void* p) {
    uint32_t a;
    asm("{ .reg .u64 t; cvta.to.shared.u64 t, %1; cvt.u32.u64 %0, t; }"
        : "=r"(a) : "l"(p));
    return a;
}
__device__ __forceinline__ void cpa16(uint32_t s, const void* g) {
    asm volatile("cp.async.cg.shared.global [%0], [%1], 16;"
                 :: "r"(s), "l"(g) : "memory");
}
__device__ __forceinline__ void ldsm4(uint32_t& r0, uint32_t& r1,
                                      uint32_t& r2, uint32_t& r3, uint32_t a) {
    asm volatile("ldmatrix.sync.aligned.m8n8.x4.shared.b16 {%0,%1,%2,%3}, [%4];"
                 : "=r"(r0), "=r"(r1), "=r"(r2), "=r"(r3) : "r"(a));
}
__device__ __forceinline__ void ldsm4t(uint32_t& r0, uint32_t& r1,
                                       uint32_t& r2, uint32_t& r3, uint32_t a) {
    asm volatile("ldmatrix.sync.aligned.m8n8.x4.trans.shared.b16 {%0,%1,%2,%3}, [%4];"
                 : "=r"(r0), "=r"(r1), "=r"(r2), "=r"(r3) : "r"(a));
}
__device__ __forceinline__ void mma_f16(float d[4], const uint32_t a[4],
                                        uint32_t b0, uint32_t b1) {
    asm("mma.sync.aligned.m16n8k16.row.col.f32.f16.f16.f32 "
        "{%0,%1,%2,%3}, {%4,%5,%6,%7}, {%8,%9}, {%0,%1,%2,%3};"
        : "+f"(d[0]), "+f"(d[1]), "+f"(d[2]), "+f"(d[3])
        : "r"(a[0]), "r"(a[1]), "r"(a[2]), "r"(a[3]), "r"(b0), "r"(b1));
}

// fused operand prep: three fp32->fp16 segments in one launch
__global__ void prep_kernel(const float* __restrict__ x,  uint32_t* __restrict__ xh,  int npx,
                            const float* __restrict__ wq, uint32_t* __restrict__ wqh, int npq,
                            const float* __restrict__ wp, uint32_t* __restrict__ wph, int npp)
{
    int i = blockIdx.x * 256 + threadIdx.x;
    const float* in;
    uint32_t* out;
    int j;
    if (i < npx)                  { in = x;  out = xh;  j = i; }
    else if (i < npx + npq)       { in = wq; out = wqh; j = i - npx; }
    else if (i < npx + npq + npp) { in = wp; out = wph; j = i - npx - npq; }
    else return;
    float2 v = ((const float2*)in)[j];
    __half2 hp = __halves2half2(__float2half_rn(v.x), __float2half_rn(v.y));
    out[j] = *(uint32_t*)&hp;
}

// ---------------------------------------------------------------------------
// fp16 GEMM:  C[m,n] = sum_k A[m,k]*W[n,k]   (both single-rounded fp16)
// CTA 128x128x32, 8 warps (4m x 2n), warp tile 32x64, ldmatrix,
// 3-stage cp.async, 2 CTAs/SM.
// MODE 0: relu on n<relu_upto, OUTPUT fp16.  MODE 1: +bias, fp32 out.
// ---------------------------------------------------------------------------
template <int MODE>
__global__ __launch_bounds__(256, 2) void f16_gemm(
    const uint32_t* __restrict__ Ah_, const uint32_t* __restrict__ Wh_,
    void* __restrict__ Cv, const float* __restrict__ bias,
    int M, int Nn, int K, int relu_upto)
{
    constexpr int PITCH = 80;
    constexpr int A_TILE = 128 * PITCH;
    constexpr int OFF_B  = A_TILE;
    constexpr int STAGE  = 2 * A_TILE;
    extern __shared__ char smem[];
    const uint32_t sb = smem_u32(smem);

    const int tid = threadIdx.x;
    const int wid = tid >> 5;
    const int lane = tid & 31;
    const int g = lane >> 2;
    const int tig = lane & 3;
    const int warp_m = (wid & 3) * 32;
    const int warp_n = (wid >> 2) * 64;
    const int m0 = blockIdx.y * 128;
    const int n0 = blockIdx.x * 128;

    const __half* Ah = (const __half*)Ah_;
    const __half* Wh = (const __half*)Wh_;

    float acc[2][8][4];
#pragma unroll
    for (int mt = 0; mt < 2; mt++)
#pragma unroll
        for (int nt = 0; nt < 8; nt++)
#pragma unroll
            for (int j = 0; j < 4; j++) acc[mt][nt][j] = 0.0f;

    const int NK = K / 32;
    const int crow = tid >> 2;
    const int cchk = tid & 3;

    auto issue = [&](int it, int s) {
        const int kt = it * 32 + cchk * 8;
        const uint32_t st = sb + (uint32_t)s * STAGE;
#pragma unroll
        for (int i = 0; i < 2; i++) {
            int r = crow + i * 64;
            uint32_t so = (uint32_t)(r * PITCH + cchk * 16);
            cpa16(st + so, Ah + (size_t)(m0 + r) * K + kt);
            cpa16(st + OFF_B + so, Wh + (size_t)(n0 + r) * K + kt);
        }
        asm volatile("cp.async.commit_group;" ::: "memory");
    };

    issue(0, 0);
    if (NK > 1) issue(1, 1);

    const uint32_t lrow = (uint32_t)(lane & 15);
    const uint32_t lchk = (uint32_t)(lane >> 4) * 16;

    for (int it = 0; it < NK; it++) {
        if (it + 1 < NK) {
            asm volatile("cp.async.wait_group 1;" ::: "memory");
        } else {
            asm volatile("cp.async.wait_group 0;" ::: "memory");
        }
        __syncthreads();
        if (it + 2 < NK) issue(it + 2, (it + 2) % 3);

        const uint32_t st = sb + (uint32_t)(it % 3) * STAGE;
        const uint32_t abase = st + (uint32_t)(warp_m + lrow) * PITCH + lchk;
        const uint32_t bbase = st + OFF_B + (uint32_t)(warp_n + lrow) * PITCH + lchk;

#pragma unroll
        for (int kk = 0; kk < 2; kk++) {
            uint32_t ah[2][4];
#pragma unroll
            for (int mt = 0; mt < 2; mt++) {
                uint32_t ao = abase + (uint32_t)(mt * 16 * PITCH + kk * 32);
                ldsm4(ah[mt][0], ah[mt][1], ah[mt][2], ah[mt][3], ao);
            }
            uint32_t b[8][2];
#pragma unroll
            for (int p = 0; p < 4; p++) {
                uint32_t bo = bbase + (uint32_t)(p * 16 * PITCH + kk * 32);
                uint32_t r0, r1, r2, r3;
                ldsm4(r0, r1, r2, r3, bo);
                b[2 * p][0] = r0; b[2 * p][1] = r2;
                b[2 * p + 1][0] = r1; b[2 * p + 1][1] = r3;
            }
#pragma unroll
            for (int nt = 0; nt < 8; nt++)
#pragma unroll
                for (int mt = 0; mt < 2; mt++)
                    mma_f16(acc[mt][nt], ah[mt], b[nt][0], b[nt][1]);
        }
    }

    // epilogue
#pragma unroll
    for (int mt = 0; mt < 2; mt++) {
        int mA = m0 + warp_m + mt * 16 + g;
#pragma unroll
        for (int nt = 0; nt < 8; nt++) {
            int n = n0 + warp_n + nt * 8 + 2 * tig;
            float e0 = acc[mt][nt][0], e1 = acc[mt][nt][1];
            float e2 = acc[mt][nt][2], e3 = acc[mt][nt][3];
            if (MODE == 0) {
                if (n < relu_upto)     { e0 = fmaxf(e0, 0.f); e2 = fmaxf(e2, 0.f); }
                if (n + 1 < relu_upto) { e1 = fmaxf(e1, 0.f); e3 = fmaxf(e3, 0.f); }
                __half* Ch = (__half*)Cv;
                __half2 h01 = __halves2half2(__float2half_rn(e0), __float2half_rn(e1));
                __half2 h23 = __halves2half2(__float2half_rn(e2), __float2half_rn(e3));
                *(uint32_t*)(Ch + (size_t)mA * Nn + n)       = *(uint32_t*)&h01;
                *(uint32_t*)(Ch + (size_t)(mA + 8) * Nn + n) = *(uint32_t*)&h23;
            } else {
                float* Cf = (float*)Cv;
                float bb0 = bias[n], bb1 = bias[n + 1];
                e0 += bb0; e1 += bb1; e2 += bb0; e3 += bb1;
                *(float2*)(Cf + (size_t)mA * Nn + n)       = make_float2(e0, e1);
                *(float2*)(Cf + (size_t)(mA + 8) * Nn + n) = make_float2(e2, e3);
            }
        }
    }
}

// ---------------------------------------------------------------------------
// vk via tensor cores, split-K x2: grid 256 = (head, half).  Each block
// reduces 2048 tokens into fp32 partial [48x32].
// ---------------------------------------------------------------------------
__global__ __launch_bounds__(128) void vk_mma_kernel(
    const __half* __restrict__ qkvh, float* __restrict__ vkp)
{
    constexpr int STAGEH = 2 * 128 * 40;
    extern __shared__ char smraw[];
    const uint32_t sbase = smem_u32(smraw);

    const int bid = blockIdx.x;
    const int head = bid >> 1;
    const int half = bid & 1;
    const int b = head >> 5;
    const int hh = head & 31;
    const int tid = threadIdx.x;
    const int wid = tid >> 5;
    const int lane = tid & 31;
    const int grp = lane >> 3;
    const int lr = lane & 7;

    float acc[3][4][4];
#pragma unroll
    for (int mt = 0; mt < 3; mt++)
#pragma unroll
        for (int nt = 0; nt < 4; nt++)
#pragma unroll
            for (int j = 0; j < 4; j++) acc[mt][nt][j] = 0.f;

    const uint32_t ones = (lane < 4) ? 0x3C003C00u : 0u;
    const uint32_t aden[4] = {ones, 0u, ones, 0u};

    auto stage = [&](int it, int s) {
        const size_t tokbase = (size_t)b * Nx + (size_t)it * 128;
#pragma unroll
        for (int j = 0; j < 8; j++) {
            int idx = tid + j * 128;
            int kv = idx >> 9;
            int r = (idx >> 2) & 127;
            int c = idx & 3;
            const __half* gp = qkvh + (tokbase + r) * NC3
                               + (kv ? 2048 : 1024) + hh * 32 + c * 8;
            uint32_t dst = sbase + (uint32_t)(s * STAGEH + kv * 5120
                                              + r * 40 + c * 8) * 2;
            cpa16(dst, gp);
        }
        asm volatile("cp.async.commit_group;" ::: "memory");
    };

    const int it0 = half * 16;
    const int it1 = it0 + 16;
    stage(it0, it0 & 1);

    for (int it = it0; it < it1; it++) {
        if (it + 1 < it1) {
            stage(it + 1, (it + 1) & 1);
            asm volatile("cp.async.wait_group 1;" ::: "memory");
        } else {
            asm volatile("cp.async.wait_group 0;" ::: "memory");
        }
        __syncthreads();

        const int s = it & 1;
        const uint32_t ks0 = sbase + (uint32_t)(s * STAGEH) * 2;
        const uint32_t vs0 = ks0 + 5120 * 2;

#pragma unroll
        for (int step = 0; step < 2; step++) {
            const int tok0 = wid * 32 + step * 16;
            uint32_t av[2][4];
#pragma unroll
            for (int mt = 0; mt < 2; mt++) {
                uint32_t ao = vs0 + (uint32_t)((tok0 + (grp >> 1) * 8 + lr) * 40
                                               + mt * 16 + (grp & 1) * 8) * 2;
                ldsm4t(av[mt][0], av[mt][1], av[mt][2], av[mt][3], ao);
            }
            uint32_t bk[4][2];
#pragma unroll
            for (int hf = 0; hf < 2; hf++) {
                uint32_t bo = ks0 + (uint32_t)((tok0 + (grp & 1) * 8 + lr) * 40
                                               + hf * 16 + (grp >> 1) * 8) * 2;
                uint32_t r0, r1, r2, r3;
                ldsm4t(r0, r1, r2, r3, bo);
                bk[2 * hf][0] = r0;     bk[2 * hf][1] = r1;
                bk[2 * hf + 1][0] = r2; bk[2 * hf + 1][1] = r3;
            }
#pragma unroll
            for (int nt = 0; nt < 4; nt++) {
#pragma unroll
                for (int mt = 0; mt < 2; mt++)
                    mma_f16(acc[mt][nt], av[mt], bk[nt][0], bk[nt][1]);
                mma_f16(acc[2][nt], aden, bk[nt][0], bk[nt][1]);
            }
        }
        __syncthreads();
    }

    // cross-warp reduce (reuse smem as float [4][48][33])
    float* red = (float*)smraw;
    const int g4 = lane >> 2;
    const int tig = lane & 3;
#pragma unroll
    for (int mt = 0; mt < 3; mt++)
#pragma unroll
        for (int nt = 0; nt < 4; nt++) {
            int m = mt * 16 + g4;
            int e = nt * 8 + 2 * tig;
            float* rb = red + (size_t)wid * 1584;
            rb[m * 33 + e]           = acc[mt][nt][0];
            rb[m * 33 + e + 1]       = acc[mt][nt][1];
            rb[(m + 8) * 33 + e]     = acc[mt][nt][2];
            rb[(m + 8) * 33 + e + 1] = acc[mt][nt][3];
        }
    __syncthreads();

#pragma unroll
    for (int i = 0; i < 12; i++) {
        int idx = tid + i * 128;
        int m = idx >> 5;
        int e = idx & 31;
        float s = red[m * 33 + e] + red[1584 + m * 33 + e]
                + red[2 * 1584 + m * 33 + e] + red[3 * 1584 + m * 33 + e];
        vkp[(size_t)bid * 1536 + idx] = s;
    }
}

// ---------------------------------------------------------------------------
// att via mma.sync: sums the two fp32 vk partials while building its vk tile.
// ---------------------------------------------------------------------------
__global__ __launch_bounds__(128) void att_kernel(
    const __half* __restrict__ qkvh, const float* __restrict__ vkp,
    uint32_t* __restrict__ ath)
{
    const int blk = blockIdx.x;
    const int nch = blk & 31;
    const int head = blk >> 5;
    const int b = head >> 5;
    const int hh = head & 31;
    const int tid = threadIdx.x;
    const int wid = tid >> 5;
    const int lane = tid & 31;

    __shared__ __half qs[128][40];
    __shared__ __half vkh[48][40];

    const size_t rowbase = (size_t)b * Nx + (size_t)nch * 128;

#pragma unroll
    for (int i = 0; i < 16; i++) {
        int idx = i * 128 + tid;
        int row = idx >> 4;
        int c = idx & 15;
        uint32_t w = *(const uint32_t*)(qkvh + (rowbase + row) * NC3 + hh * 32 + 2 * c);
        *(uint32_t*)&qs[row][2 * c] = w;
    }
    // build vk tile: sum two fp32 partials, round to fp16
    const float* p0 = vkp + (size_t)(2 * head) * 1536;
    const float* p1 = p0 + 1536;
#pragma unroll
    for (int i = 0; i < 12; i++) {
        int idx = i * 128 + tid;                     // 0..1535
        int m = idx >> 5;
        int e = idx & 31;
        vkh[m][e] = __float2half_rn(p0[idx] + p1[idx]);
    }
    __syncthreads();

    const uint32_t lrow = (uint32_t)(lane & 15);
    const uint32_t lchk = (uint32_t)(lane >> 4) * 16;
    const uint32_t qsb = smem_u32(qs);
    const uint32_t vkb = smem_u32(vkh);

    uint32_t a[2][2][4];
#pragma unroll
    for (int mt = 0; mt < 2; mt++)
#pragma unroll
        for (int kk = 0; kk < 2; kk++) {
            uint32_t ao = qsb + (uint32_t)((wid * 32 + mt * 16 + lrow) * 80) + lchk + kk * 32;
            ldsm4(a[mt][kk][0], a[mt][kk][1], a[mt][kk][2], a[mt][kk][3], ao);
        }
    uint32_t bfr[6][2][2];
#pragma unroll
    for (int p = 0; p < 3; p++)
#pragma unroll
        for (int kk = 0; kk < 2; kk++) {
            uint32_t bo = vkb + (uint32_t)((p * 16 + lrow) * 80) + lchk + kk * 32;
            uint32_t r0, r1, r2, r3;
            ldsm4(r0, r1, r2, r3, bo);
            bfr[2 * p][kk][0] = r0;     bfr[2 * p][kk][1] = r2;
            bfr[2 * p + 1][kk][0] = r1; bfr[2 * p + 1][kk][1] = r3;
        }

    float c[2][5][4];
#pragma unroll
    for (int mt = 0; mt < 2; mt++)
#pragma unroll
        for (int nt = 0; nt < 5; nt++) {
#pragma unroll
            for (int j = 0; j < 4; j++) c[mt][nt][j] = 0.f;
#pragma unroll
            for (int kk = 0; kk < 2; kk++)
                mma_f16(c[mt][nt], a[mt][kk], bfr[nt][kk][0], bfr[nt][kk][1]);
        }

    const int g = lane >> 2;
    const int tig = lane & 3;
#pragma unroll
    for (int mt = 0; mt < 2; mt++) {
        float d0 = __shfl_sync(0xffffffffu, c[mt][4][0], lane & 28);
        float d1 = __shfl_sync(0xffffffffu, c[mt][4][2], lane & 28);
        float i0 = 1.0f / (d0 + EPSV);
        float i1 = 1.0f / (d1 + EPSV);
        size_t t0 = rowbase + (size_t)(wid * 32 + mt * 16 + g);
#pragma unroll
        for (int nt = 0; nt < 4; nt++) {
            __half2 h0 = __halves2half2(__float2half_rn(c[mt][nt][0] * i0),
                                        __float2half_rn(c[mt][nt][1] * i0));
            __half2 h1 = __halves2half2(__float2half_rn(c[mt][nt][2] * i1),
                                        __float2half_rn(c[mt][nt][3] * i1));
            ath[t0 * 512 + hh * 16 + nt * 4 + tig]       = *(uint32_t*)&h0;
            ath[(t0 + 8) * 512 + hh * 16 + nt * 4 + tig] = *(uint32_t*)&h1;
        }
    }
}

// ---------------------------------------------------------------------------
extern "C" void kernel_launch(void* const* d_in, const int* in_sizes, int n_in,
                              void* d_out, int out_size)
{
    const float* x     = (const float*)d_in[0];
    const float* Wqkv  = (const float*)d_in[1];
    const float* Wproj = (const float*)d_in[2];
    const float* bproj = (const float*)d_in[3];
    float* out = (float*)d_out;

    __half* qkvh;
    float* vkp;
    uint32_t *xh, *ath, *wqh, *wph;
    cudaGetSymbolAddress((void**)&qkvh, g_qkvh);
    cudaGetSymbolAddress((void**)&vkp,  g_vkp);
    cudaGetSymbolAddress((void**)&xh,   g_xh);
    cudaGetSymbolAddress((void**)&ath,  g_ath);
    cudaGetSymbolAddress((void**)&wqh,  g_wqh);
    cudaGetSymbolAddress((void**)&wph,  g_wph);

    const int M = Bx * Nx;   // 16384

    const int smem = 3 * 2 * 10240;   // 61440 B per CTA (2 CTAs/SM)
    cudaFuncSetAttribute(f16_gemm<0>,
                         cudaFuncAttributeMaxDynamicSharedMemorySize, smem);
    cudaFuncSetAttribute(f16_gemm<1>,
                         cudaFuncAttributeMaxDynamicSharedMemorySize, smem);

    // 0) fused operand prep (fp32 -> fp16)
    {
        int npx = M * Cx / 2;
        int npq = NC3 * Cx / 2;
        int npp = Cx * Cx / 2;
        int tot = npx + npq + npp;
        prep_kernel<<<(tot + 255) / 256, 256>>>(x, xh, npx, Wqkv, wqh, npq,
                                                Wproj, wph, npp);
    }

    // 1) qkv = x @ Wqkv^T -> fp16 (relu fused on n < 2048)
    f16_gemm<0><<<dim3(NC3 / 128, M / 128), 256, smem>>>(
        xh, wqh, qkvh, nullptr, M, NC3, Cx, 2 * Cx);

    // 2) vk split-K x2 -> fp32 partials
    vk_mma_kernel<<<256, 128, 40960>>>(qkvh, vkp);

    // 3) attention normalize (sums partials) -> ath fp16
    att_kernel<<<4096, 128>>>(qkvh, vkp, ath);

    // 4) out = att @ Wproj^T + b  (fp32 out)
    f16_gemm<1><<<dim3(Cx / 128, M / 128), 256, smem>>>(
        ath, wph, out, bproj, M, Cx, Cx, 0);
}

// round 15
// speedup vs baseline: 2.0070x; 1.0164x over previous
#include <cuda_runtime.h>
#include <cuda_fp16.h>
#include <cstdint>

#define Bx 4
#define Nx 4096
#define Cx 1024
#define NC3 3072
#define EPSV 1e-15f

// Scratch (device globals — no allocation allowed)
__device__ __half   g_qkvh[(size_t)Bx * Nx * NC3];         // 96 MB fp16 qkv
__device__ uint32_t g_xh[(size_t)Bx * Nx * Cx / 2];        // x fp16
__device__ uint32_t g_ath[(size_t)Bx * Nx * Cx / 2];       // att fp16
__device__ uint32_t g_wqh[(size_t)NC3 * Cx / 2];           // Wqkv fp16
__device__ uint32_t g_wph[(size_t)Cx * Cx / 2];            // Wproj fp16
__device__ float    g_vkp[256 * 1536];                     // vk fp32 partials

__device__ __forceinline__ uint32_t smem_u32(const void* p) {
    uint32_t a;
    asm("{ .reg .u64 t; cvta.to.shared.u64 t, %1; cvt.u32.u64 %0, t; }"
        : "=r"(a) : "l"(p));
    return a;
}
__device__ __forceinline__ void cpa16(uint32_t s, const void* g) {
    asm volatile("cp.async.cg.shared.global [%0], [%1], 16;"
                 :: "r"(s), "l"(g) : "memory");
}
__device__ __forceinline__ void ldsm4(uint32_t& r0, uint32_t& r1,
                                      uint32_t& r2, uint32_t& r3, uint32_t a) {
    asm volatile("ldmatrix.sync.aligned.m8n8.x4.shared.b16 {%0,%1,%2,%3}, [%4];"
                 : "=r"(r0), "=r"(r1), "=r"(r2), "=r"(r3) : "r"(a));
}
__device__ __forceinline__ void ldsm4t(uint32_t& r0, uint32_t& r1,
                                       uint32_t& r2, uint32_t& r3, uint32_t a) {
    asm volatile("ldmatrix.sync.aligned.m8n8.x4.trans.shared.b16 {%0,%1,%2,%3}, [%4];"
                 : "=r"(r0), "=r"(r1), "=r"(r2), "=r"(r3) : "r"(a));
}
__device__ __forceinline__ void mma_f16(float d[4], const uint32_t a[4],
                                        uint32_t b0, uint32_t b1) {
    asm("mma.sync.aligned.m16n8k16.row.col.f32.f16.f16.f32 "
        "{%0,%1,%2,%3}, {%4,%5,%6,%7}, {%8,%9}, {%0,%1,%2,%3};"
        : "+f"(d[0]), "+f"(d[1]), "+f"(d[2]), "+f"(d[3])
        : "r"(a[0]), "r"(a[1]), "r"(a[2]), "r"(a[3]), "r"(b0), "r"(b1));
}

// fused operand prep: three fp32->fp16 segments, 4 floats (2 pairs)/thread
__global__ void prep_kernel(const float* __restrict__ x,  uint32_t* __restrict__ xh,  int ngx,
                            const float* __restrict__ wq, uint32_t* __restrict__ wqh, int ngq,
                            const float* __restrict__ wp, uint32_t* __restrict__ wph, int ngp)
{
    int i = blockIdx.x * 256 + threadIdx.x;
    const float* in;
    uint32_t* out;
    int j;
    if (i < ngx)                  { in = x;  out = xh;  j = i; }
    else if (i < ngx + ngq)       { in = wq; out = wqh; j = i - ngx; }
    else if (i < ngx + ngq + ngp) { in = wp; out = wph; j = i - ngx - ngq; }
    else return;
    float4 v = ((const float4*)in)[j];
    __half2 h0 = __halves2half2(__float2half_rn(v.x), __float2half_rn(v.y));
    __half2 h1 = __halves2half2(__float2half_rn(v.z), __float2half_rn(v.w));
    uint2 o;
    o.x = *(uint32_t*)&h0;
    o.y = *(uint32_t*)&h1;
    ((uint2*)out)[j] = o;
}

// ---------------------------------------------------------------------------
// fp16 GEMM:  C[m,n] = sum_k A[m,k]*W[n,k]   (both single-rounded fp16)
// CTA 128x128x32, 8 warps (4m x 2n), warp tile 32x64, ldmatrix,
// 3-stage cp.async, 2 CTAs/SM.
// MODE 0: relu on n<relu_upto, OUTPUT fp16.  MODE 1: +bias, fp32 out.
// ---------------------------------------------------------------------------
template <int MODE>
__global__ __launch_bounds__(256, 2) void f16_gemm(
    const uint32_t* __restrict__ Ah_, const uint32_t* __restrict__ Wh_,
    void* __restrict__ Cv, const float* __restrict__ bias,
    int M, int Nn, int K, int relu_upto)
{
    constexpr int PITCH = 80;
    constexpr int A_TILE = 128 * PITCH;
    constexpr int OFF_B  = A_TILE;
    constexpr int STAGE  = 2 * A_TILE;
    extern __shared__ char smem[];
    const uint32_t sb = smem_u32(smem);

    const int tid = threadIdx.x;
    const int wid = tid >> 5;
    const int lane = tid & 31;
    const int g = lane >> 2;
    const int tig = lane & 3;
    const int warp_m = (wid & 3) * 32;
    const int warp_n = (wid >> 2) * 64;
    const int m0 = blockIdx.y * 128;
    const int n0 = blockIdx.x * 128;

    const __half* Ah = (const __half*)Ah_;
    const __half* Wh = (const __half*)Wh_;

    float acc[2][8][4];
#pragma unroll
    for (int mt = 0; mt < 2; mt++)
#pragma unroll
        for (int nt = 0; nt < 8; nt++)
#pragma unroll
            for (int j = 0; j < 4; j++) acc[mt][nt][j] = 0.0f;

    const int NK = K / 32;
    const int crow = tid >> 2;
    const int cchk = tid & 3;

    auto issue = [&](int it, int s) {
        const int kt = it * 32 + cchk * 8;
        const uint32_t st = sb + (uint32_t)s * STAGE;
#pragma unroll
        for (int i = 0; i < 2; i++) {
            int r = crow + i * 64;
            uint32_t so = (uint32_t)(r * PITCH + cchk * 16);
            cpa16(st + so, Ah + (size_t)(m0 + r) * K + kt);
            cpa16(st + OFF_B + so, Wh + (size_t)(n0 + r) * K + kt);
        }
        asm volatile("cp.async.commit_group;" ::: "memory");
    };

    issue(0, 0);
    if (NK > 1) issue(1, 1);

    const uint32_t lrow = (uint32_t)(lane & 15);
    const uint32_t lchk = (uint32_t)(lane >> 4) * 16;

    for (int it = 0; it < NK; it++) {
        if (it + 1 < NK) {
            asm volatile("cp.async.wait_group 1;" ::: "memory");
        } else {
            asm volatile("cp.async.wait_group 0;" ::: "memory");
        }
        __syncthreads();
        if (it + 2 < NK) issue(it + 2, (it + 2) % 3);

        const uint32_t st = sb + (uint32_t)(it % 3) * STAGE;
        const uint32_t abase = st + (uint32_t)(warp_m + lrow) * PITCH + lchk;
        const uint32_t bbase = st + OFF_B + (uint32_t)(warp_n + lrow) * PITCH + lchk;

#pragma unroll
        for (int kk = 0; kk < 2; kk++) {
            uint32_t ah[2][4];
#pragma unroll
            for (int mt = 0; mt < 2; mt++) {
                uint32_t ao = abase + (uint32_t)(mt * 16 * PITCH + kk * 32);
                ldsm4(ah[mt][0], ah[mt][1], ah[mt][2], ah[mt][3], ao);
            }
            uint32_t b[8][2];
#pragma unroll
            for (int p = 0; p < 4; p++) {
                uint32_t bo = bbase + (uint32_t)(p * 16 * PITCH + kk * 32);
                uint32_t r0, r1, r2, r3;
                ldsm4(r0, r1, r2, r3, bo);
                b[2 * p][0] = r0; b[2 * p][1] = r2;
                b[2 * p + 1][0] = r1; b[2 * p + 1][1] = r3;
            }
#pragma unroll
            for (int nt = 0; nt < 8; nt++)
#pragma unroll
                for (int mt = 0; mt < 2; mt++)
                    mma_f16(acc[mt][nt], ah[mt], b[nt][0], b[nt][1]);
        }
    }

    // epilogue
#pragma unroll
    for (int mt = 0; mt < 2; mt++) {
        int mA = m0 + warp_m + mt * 16 + g;
#pragma unroll
        for (int nt = 0; nt < 8; nt++) {
            int n = n0 + warp_n + nt * 8 + 2 * tig;
            float e0 = acc[mt][nt][0], e1 = acc[mt][nt][1];
            float e2 = acc[mt][nt][2], e3 = acc[mt][nt][3];
            if (MODE == 0) {
                if (n < relu_upto)     { e0 = fmaxf(e0, 0.f); e2 = fmaxf(e2, 0.f); }
                if (n + 1 < relu_upto) { e1 = fmaxf(e1, 0.f); e3 = fmaxf(e3, 0.f); }
                __half* Ch = (__half*)Cv;
                __half2 h01 = __halves2half2(__float2half_rn(e0), __float2half_rn(e1));
                __half2 h23 = __halves2half2(__float2half_rn(e2), __float2half_rn(e3));
                *(uint32_t*)(Ch + (size_t)mA * Nn + n)       = *(uint32_t*)&h01;
                *(uint32_t*)(Ch + (size_t)(mA + 8) * Nn + n) = *(uint32_t*)&h23;
            } else {
                float* Cf = (float*)Cv;
                float bb0 = bias[n], bb1 = bias[n + 1];
                e0 += bb0; e1 += bb1; e2 += bb0; e3 += bb1;
                *(float2*)(Cf + (size_t)mA * Nn + n)       = make_float2(e0, e1);
                *(float2*)(Cf + (size_t)(mA + 8) * Nn + n) = make_float2(e2, e3);
            }
        }
    }
}

// ---------------------------------------------------------------------------
// vk via tensor cores, split-K x2 (unchanged from R14).
// ---------------------------------------------------------------------------
__global__ __launch_bounds__(128) void vk_mma_kernel(
    const __half* __restrict__ qkvh, float* __restrict__ vkp)
{
    constexpr int STAGEH = 2 * 128 * 40;
    extern __shared__ char smraw[];
    const uint32_t sbase = smem_u32(smraw);

    const int bid = blockIdx.x;
    const int head = bid >> 1;
    const int half = bid & 1;
    const int b = head >> 5;
    const int hh = head & 31;
    const int tid = threadIdx.x;
    const int wid = tid >> 5;
    const int lane = tid & 31;
    const int grp = lane >> 3;
    const int lr = lane & 7;

    float acc[3][4][4];
#pragma unroll
    for (int mt = 0; mt < 3; mt++)
#pragma unroll
        for (int nt = 0; nt < 4; nt++)
#pragma unroll
            for (int j = 0; j < 4; j++) acc[mt][nt][j] = 0.f;

    const uint32_t ones = (lane < 4) ? 0x3C003C00u : 0u;
    const uint32_t aden[4] = {ones, 0u, ones, 0u};

    auto stage = [&](int it, int s) {
        const size_t tokbase = (size_t)b * Nx + (size_t)it * 128;
#pragma unroll
        for (int j = 0; j < 8; j++) {
            int idx = tid + j * 128;
            int kv = idx >> 9;
            int r = (idx >> 2) & 127;
            int c = idx & 3;
            const __half* gp = qkvh + (tokbase + r) * NC3
                               + (kv ? 2048 : 1024) + hh * 32 + c * 8;
            uint32_t dst = sbase + (uint32_t)(s * STAGEH + kv * 5120
                                              + r * 40 + c * 8) * 2;
            cpa16(dst, gp);
        }
        asm volatile("cp.async.commit_group;" ::: "memory");
    };

    const int it0 = half * 16;
    const int it1 = it0 + 16;
    stage(it0, it0 & 1);

    for (int it = it0; it < it1; it++) {
        if (it + 1 < it1) {
            stage(it + 1, (it + 1) & 1);
            asm volatile("cp.async.wait_group 1;" ::: "memory");
        } else {
            asm volatile("cp.async.wait_group 0;" ::: "memory");
        }
        __syncthreads();

        const int s = it & 1;
        const uint32_t ks0 = sbase + (uint32_t)(s * STAGEH) * 2;
        const uint32_t vs0 = ks0 + 5120 * 2;

#pragma unroll
        for (int step = 0; step < 2; step++) {
            const int tok0 = wid * 32 + step * 16;
            uint32_t av[2][4];
#pragma unroll
            for (int mt = 0; mt < 2; mt++) {
                uint32_t ao = vs0 + (uint32_t)((tok0 + (grp >> 1) * 8 + lr) * 40
                                               + mt * 16 + (grp & 1) * 8) * 2;
                ldsm4t(av[mt][0], av[mt][1], av[mt][2], av[mt][3], ao);
            }
            uint32_t bk[4][2];
#pragma unroll
            for (int hf = 0; hf < 2; hf++) {
                uint32_t bo = ks0 + (uint32_t)((tok0 + (grp & 1) * 8 + lr) * 40
                                               + hf * 16 + (grp >> 1) * 8) * 2;
                uint32_t r0, r1, r2, r3;
                ldsm4t(r0, r1, r2, r3, bo);
                bk[2 * hf][0] = r0;     bk[2 * hf][1] = r1;
                bk[2 * hf + 1][0] = r2; bk[2 * hf + 1][1] = r3;
            }
#pragma unroll
            for (int nt = 0; nt < 4; nt++) {
#pragma unroll
                for (int mt = 0; mt < 2; mt++)
                    mma_f16(acc[mt][nt], av[mt], bk[nt][0], bk[nt][1]);
                mma_f16(acc[2][nt], aden, bk[nt][0], bk[nt][1]);
            }
        }
        __syncthreads();
    }

    float* red = (float*)smraw;
    const int g4 = lane >> 2;
    const int tig = lane & 3;
#pragma unroll
    for (int mt = 0; mt < 3; mt++)
#pragma unroll
        for (int nt = 0; nt < 4; nt++) {
            int m = mt * 16 + g4;
            int e = nt * 8 + 2 * tig;
            float* rb = red + (size_t)wid * 1584;
            rb[m * 33 + e]           = acc[mt][nt][0];
            rb[m * 33 + e + 1]       = acc[mt][nt][1];
            rb[(m + 8) * 33 + e]     = acc[mt][nt][2];
            rb[(m + 8) * 33 + e + 1] = acc[mt][nt][3];
        }
    __syncthreads();

#pragma unroll
    for (int i = 0; i < 12; i++) {
        int idx = tid + i * 128;
        int m = idx >> 5;
        int e = idx & 31;
        float s = red[m * 33 + e] + red[1584 + m * 33 + e]
                + red[2 * 1584 + m * 33 + e] + red[3 * 1584 + m * 33 + e];
        vkp[(size_t)bid * 1536 + idx] = s;
    }
}

// ---------------------------------------------------------------------------
// att via mma.sync: 256 threads, 256 tokens per CTA (grid 2048).
// Sums the two fp32 vk partials while building its vk tile.
// ---------------------------------------------------------------------------
__global__ __launch_bounds__(256) void att_kernel(
    const __half* __restrict__ qkvh, const float* __restrict__ vkp,
    uint32_t* __restrict__ ath)
{
    const int blk = blockIdx.x;
    const int nch = blk & 15;                        // 16 chunks of 256 tokens
    const int head = blk >> 4;
    const int b = head >> 5;
    const int hh = head & 31;
    const int tid = threadIdx.x;
    const int wid = tid >> 5;                        // 0..7
    const int lane = tid & 31;

    __shared__ __half qs[256][40];
    __shared__ __half vkh[48][40];

    const size_t rowbase = (size_t)b * Nx + (size_t)nch * 256;

    // stage q: 256 rows x 16 words
#pragma unroll
    for (int i = 0; i < 16; i++) {
        int idx = i * 256 + tid;
        int row = idx >> 4;
        int c = idx & 15;
        uint32_t w = *(const uint32_t*)(qkvh + (rowbase + row) * NC3 + hh * 32 + 2 * c);
        *(uint32_t*)&qs[row][2 * c] = w;
    }
    // build vk tile: sum two fp32 partials, round to fp16
    const float* p0 = vkp + (size_t)(2 * head) * 1536;
    const float* p1 = p0 + 1536;
#pragma unroll
    for (int i = 0; i < 6; i++) {
        int idx = i * 256 + tid;                     // 0..1535
        int m = idx >> 5;
        int e = idx & 31;
        vkh[m][e] = __float2half_rn(p0[idx] + p1[idx]);
    }
    __syncthreads();

    const uint32_t lrow = (uint32_t)(lane & 15);
    const uint32_t lchk = (uint32_t)(lane >> 4) * 16;
    const uint32_t qsb = smem_u32(qs);
    const uint32_t vkb = smem_u32(vkh);

    uint32_t a[2][2][4];
#pragma unroll
    for (int mt = 0; mt < 2; mt++)
#pragma unroll
        for (int kk = 0; kk < 2; kk++) {
            uint32_t ao = qsb + (uint32_t)((wid * 32 + mt * 16 + lrow) * 80) + lchk + kk * 32;
            ldsm4(a[mt][kk][0], a[mt][kk][1], a[mt][kk][2], a[mt][kk][3], ao);
        }
    uint32_t bfr[6][2][2];
#pragma unroll
    for (int p = 0; p < 3; p++)
#pragma unroll
        for (int kk = 0; kk < 2; kk++) {
            uint32_t bo = vkb + (uint32_t)((p * 16 + lrow) * 80) + lchk + kk * 32;
            uint32_t r0, r1, r2, r3;
            ldsm4(r0, r1, r2, r3, bo);
            bfr[2 * p][kk][0] = r0;     bfr[2 * p][kk][1] = r2;
            bfr[2 * p + 1][kk][0] = r1; bfr[2 * p + 1][kk][1] = r3;
        }

    float c[2][5][4];
#pragma unroll
    for (int mt = 0; mt < 2; mt++)
#pragma unroll
        for (int nt = 0; nt < 5; nt++) {
#pragma unroll
            for (int j = 0; j < 4; j++) c[mt][nt][j] = 0.f;
#pragma unroll
            for (int kk = 0; kk < 2; kk++)
                mma_f16(c[mt][nt], a[mt][kk], bfr[nt][kk][0], bfr[nt][kk][1]);
        }

    const int g = lane >> 2;
    const int tig = lane & 3;
#pragma unroll
    for (int mt = 0; mt < 2; mt++) {
        float d0 = __shfl_sync(0xffffffffu, c[mt][4][0], lane & 28);
        float d1 = __shfl_sync(0xffffffffu, c[mt][4][2], lane & 28);
        float i0 = 1.0f / (d0 + EPSV);
        float i1 = 1.0f / (d1 + EPSV);
        size_t t0 = rowbase + (size_t)(wid * 32 + mt * 16 + g);
#pragma unroll
        for (int nt = 0; nt < 4; nt++) {
            __half2 h0 = __halves2half2(__float2half_rn(c[mt][nt][0] * i0),
                                        __float2half_rn(c[mt][nt][1] * i0));
            __half2 h1 = __halves2half2(__float2half_rn(c[mt][nt][2] * i1),
                                        __float2half_rn(c[mt][nt][3] * i1));
            ath[t0 * 512 + hh * 16 + nt * 4 + tig]       = *(uint32_t*)&h0;
            ath[(t0 + 8) * 512 + hh * 16 + nt * 4 + tig] = *(uint32_t*)&h1;
        }
    }
}

// ---------------------------------------------------------------------------
extern "C" void kernel_launch(void* const* d_in, const int* in_sizes, int n_in,
                              void* d_out, int out_size)
{
    const float* x     = (const float*)d_in[0];
    const float* Wqkv  = (const float*)d_in[1];
    const float* Wproj = (const float*)d_in[2];
    const float* bproj = (const float*)d_in[3];
    float* out = (float*)d_out;

    __half* qkvh;
    float* vkp;
    uint32_t *xh, *ath, *wqh, *wph;
    cudaGetSymbolAddress((void**)&qkvh, g_qkvh);
    cudaGetSymbolAddress((void**)&vkp,  g_vkp);
    cudaGetSymbolAddress((void**)&xh,   g_xh);
    cudaGetSymbolAddress((void**)&ath,  g_ath);
    cudaGetSymbolAddress((void**)&wqh,  g_wqh);
    cudaGetSymbolAddress((void**)&wph,  g_wph);

    const int M = Bx * Nx;   // 16384

    const int smem = 3 * 2 * 10240;   // 61440 B per CTA (2 CTAs/SM)
    cudaFuncSetAttribute(f16_gemm<0>,
                         cudaFuncAttributeMaxDynamicSharedMemorySize, smem);
    cudaFuncSetAttribute(f16_gemm<1>,
                         cudaFuncAttributeMaxDynamicSharedMemorySize, smem);

    // 0) fused operand prep (fp32 -> fp16), 4 floats per thread
    {
        int ngx = M * Cx / 4;
        int ngq = NC3 * Cx / 4;
        int ngp = Cx * Cx / 4;
        int tot = ngx + ngq + ngp;
        prep_kernel<<<(tot + 255) / 256, 256>>>(x, xh, ngx, Wqkv, wqh, ngq,
                                                Wproj, wph, ngp);
    }

    // 1) qkv = x @ Wqkv^T -> fp16 (relu fused on n < 2048)
    f16_gemm<0><<<dim3(NC3 / 128, M / 128), 256, smem>>>(
        xh, wqh, qkvh, nullptr, M, NC3, Cx, 2 * Cx);

    // 2) vk split-K x2 -> fp32 partials
    vk_mma_kernel<<<256, 128, 40960>>>(qkvh, vkp);

    // 3) attention normalize (256 tokens/CTA) -> ath fp16
    att_kernel<<<2048, 256>>>(qkvh, vkp, ath);

    // 4) out = att @ Wproj^T + b  (fp32 out)
    f16_gemm<1><<<dim3(Cx / 128, M / 128), 256, smem>>>(
        ath, wph, out, bproj, M, Cx, Cx, 0);
}

// round 16
// speedup vs baseline: 2.2543x; 1.1232x over previous
#include <cuda_runtime.h>
#include <cuda_fp16.h>
#include <cstdint>

#define Bx 4
#define Nx 4096
#define Cx 1024
#define NC3 3072
#define EPSV 1e-15f

// Scratch (device globals — no allocation allowed)
__device__ __half   g_qkvh[(size_t)Bx * Nx * NC3];         // 96 MB fp16 qkv
__device__ uint32_t g_xh[(size_t)Bx * Nx * Cx / 2];        // x fp16
__device__ uint32_t g_ath[(size_t)Bx * Nx * Cx / 2];       // att fp16
__device__ uint32_t g_wqh[(size_t)NC3 * Cx / 2];           // Wqkv fp16
__device__ uint32_t g_wph[(size_t)Cx * Cx / 2];            // Wproj fp16
__device__ float    g_vkp[256 * 1536];                     // vk fp32 partials

__device__ __forceinline__ uint32_t smem_u32(const void* p) {
    uint32_t a;
    asm("{ .reg .u64 t; cvta.to.shared.u64 t, %1; cvt.u32.u64 %0, t; }"
        : "=r"(a) : "l"(p));
    return a;
}
__device__ __forceinline__ void cpa16(uint32_t s, const void* g) {
    asm volatile("cp.async.cg.shared.global [%0], [%1], 16;"
                 :: "r"(s), "l"(g) : "memory");
}
__device__ __forceinline__ void ldsm4(uint32_t& r0, uint32_t& r1,
                                      uint32_t& r2, uint32_t& r3, uint32_t a) {
    asm volatile("ldmatrix.sync.aligned.m8n8.x4.shared.b16 {%0,%1,%2,%3}, [%4];"
                 : "=r"(r0), "=r"(r1), "=r"(r2), "=r"(r3) : "r"(a));
}
__device__ __forceinline__ void ldsm4t(uint32_t& r0, uint32_t& r1,
                                       uint32_t& r2, uint32_t& r3, uint32_t a) {
    asm volatile("ldmatrix.sync.aligned.m8n8.x4.trans.shared.b16 {%0,%1,%2,%3}, [%4];"
                 : "=r"(r0), "=r"(r1), "=r"(r2), "=r"(r3) : "r"(a));
}
__device__ __forceinline__ void mma_f16(float d[4], const uint32_t a[4],
                                        uint32_t b0, uint32_t b1) {
    asm("mma.sync.aligned.m16n8k16.row.col.f32.f16.f16.f32 "
        "{%0,%1,%2,%3}, {%4,%5,%6,%7}, {%8,%9}, {%0,%1,%2,%3};"
        : "+f"(d[0]), "+f"(d[1]), "+f"(d[2]), "+f"(d[3])
        : "r"(a[0]), "r"(a[1]), "r"(a[2]), "r"(a[3]), "r"(b0), "r"(b1));
}

// fused operand prep: three fp32->fp16 segments, 4 floats (2 pairs)/thread
__global__ void prep_kernel(const float* __restrict__ x,  uint32_t* __restrict__ xh,  int ngx,
                            const float* __restrict__ wq, uint32_t* __restrict__ wqh, int ngq,
                            const float* __restrict__ wp, uint32_t* __restrict__ wph, int ngp)
{
    int i = blockIdx.x * 256 + threadIdx.x;
    const float* in;
    uint32_t* out;
    int j;
    if (i < ngx)                  { in = x;  out = xh;  j = i; }
    else if (i < ngx + ngq)       { in = wq; out = wqh; j = i - ngx; }
    else if (i < ngx + ngq + ngp) { in = wp; out = wph; j = i - ngx - ngq; }
    else return;
    float4 v = ((const float4*)in)[j];
    __half2 h0 = __halves2half2(__float2half_rn(v.x), __float2half_rn(v.y));
    __half2 h1 = __halves2half2(__float2half_rn(v.z), __float2half_rn(v.w));
    uint2 o;
    o.x = *(uint32_t*)&h0;
    o.y = *(uint32_t*)&h1;
    ((uint2*)out)[j] = o;
}

// ---------------------------------------------------------------------------
// fp16 GEMM:  C[m,n] = sum_k A[m,k]*W[n,k]   (both single-rounded fp16)
// CTA 128x128x64, 8 warps (4m x 2n), warp tile 32x64, ldmatrix,
// 3-stage cp.async, ONE barrier per 64-K, 2 CTAs/SM.
// MODE 0: relu on n<relu_upto, OUTPUT fp16.  MODE 1: +bias, fp32 out.
// ---------------------------------------------------------------------------
template <int MODE>
__global__ __launch_bounds__(256, 2) void f16_gemm(
    const uint32_t* __restrict__ Ah_, const uint32_t* __restrict__ Wh_,
    void* __restrict__ Cv, const float* __restrict__ bias,
    int M, int Nn, int K, int relu_upto)
{
    constexpr int PITCH = 144;                       // 64 halfs + 8 pad (bytes)
    constexpr int A_TILE = 128 * PITCH;              // 18432
    constexpr int OFF_B  = A_TILE;
    constexpr int STAGE  = 2 * A_TILE;               // 36864
    extern __shared__ char smem[];
    const uint32_t sb = smem_u32(smem);

    const int tid = threadIdx.x;
    const int wid = tid >> 5;
    const int lane = tid & 31;
    const int g = lane >> 2;
    const int tig = lane & 3;
    const int warp_m = (wid & 3) * 32;
    const int warp_n = (wid >> 2) * 64;
    const int m0 = blockIdx.y * 128;
    const int n0 = blockIdx.x * 128;

    const __half* Ah = (const __half*)Ah_;
    const __half* Wh = (const __half*)Wh_;

    float acc[2][8][4];
#pragma unroll
    for (int mt = 0; mt < 2; mt++)
#pragma unroll
        for (int nt = 0; nt < 8; nt++)
#pragma unroll
            for (int j = 0; j < 4; j++) acc[mt][nt][j] = 0.0f;

    const int NK = K / 64;                           // 64-K tiles
    const int crow = tid >> 3;                       // 0..31
    const int cchk = tid & 7;                        // 16B chunk (8 halfs)

    auto issue = [&](int it, int s) {
        const int kt = it * 64 + cchk * 8;
        const uint32_t st = sb + (uint32_t)s * STAGE;
#pragma unroll
        for (int i = 0; i < 4; i++) {
            int r = crow + i * 32;
            uint32_t so = (uint32_t)(r * PITCH + cchk * 16);
            cpa16(st + so, Ah + (size_t)(m0 + r) * K + kt);
            cpa16(st + OFF_B + so, Wh + (size_t)(n0 + r) * K + kt);
        }
        asm volatile("cp.async.commit_group;" ::: "memory");
    };

    issue(0, 0);
    if (NK > 1) issue(1, 1);

    const uint32_t lrow = (uint32_t)(lane & 15);
    const uint32_t lchk = (uint32_t)(lane >> 4) * 16;

    for (int it = 0; it < NK; it++) {
        if (it + 1 < NK) {
            asm volatile("cp.async.wait_group 1;" ::: "memory");
        } else {
            asm volatile("cp.async.wait_group 0;" ::: "memory");
        }
        __syncthreads();
        if (it + 2 < NK) issue(it + 2, (it + 2) % 3);

        const uint32_t st = sb + (uint32_t)(it % 3) * STAGE;
        const uint32_t abase = st + (uint32_t)(warp_m + lrow) * PITCH + lchk;
        const uint32_t bbase = st + OFF_B + (uint32_t)(warp_n + lrow) * PITCH + lchk;

#pragma unroll
        for (int kk = 0; kk < 4; kk++) {
            uint32_t ah[2][4];
#pragma unroll
            for (int mt = 0; mt < 2; mt++) {
                uint32_t ao = abase + (uint32_t)(mt * 16 * PITCH + kk * 32);
                ldsm4(ah[mt][0], ah[mt][1], ah[mt][2], ah[mt][3], ao);
            }
            uint32_t b[8][2];
#pragma unroll
            for (int p = 0; p < 4; p++) {
                uint32_t bo = bbase + (uint32_t)(p * 16 * PITCH + kk * 32);
                uint32_t r0, r1, r2, r3;
                ldsm4(r0, r1, r2, r3, bo);
                b[2 * p][0] = r0; b[2 * p][1] = r2;
                b[2 * p + 1][0] = r1; b[2 * p + 1][1] = r3;
            }
#pragma unroll
            for (int nt = 0; nt < 8; nt++)
#pragma unroll
                for (int mt = 0; mt < 2; mt++)
                    mma_f16(acc[mt][nt], ah[mt], b[nt][0], b[nt][1]);
        }
    }

    // epilogue
#pragma unroll
    for (int mt = 0; mt < 2; mt++) {
        int mA = m0 + warp_m + mt * 16 + g;
#pragma unroll
        for (int nt = 0; nt < 8; nt++) {
            int n = n0 + warp_n + nt * 8 + 2 * tig;
            float e0 = acc[mt][nt][0], e1 = acc[mt][nt][1];
            float e2 = acc[mt][nt][2], e3 = acc[mt][nt][3];
            if (MODE == 0) {
                if (n < relu_upto)     { e0 = fmaxf(e0, 0.f); e2 = fmaxf(e2, 0.f); }
                if (n + 1 < relu_upto) { e1 = fmaxf(e1, 0.f); e3 = fmaxf(e3, 0.f); }
                __half* Ch = (__half*)Cv;
                __half2 h01 = __halves2half2(__float2half_rn(e0), __float2half_rn(e1));
                __half2 h23 = __halves2half2(__float2half_rn(e2), __float2half_rn(e3));
                *(uint32_t*)(Ch + (size_t)mA * Nn + n)       = *(uint32_t*)&h01;
                *(uint32_t*)(Ch + (size_t)(mA + 8) * Nn + n) = *(uint32_t*)&h23;
            } else {
                float* Cf = (float*)Cv;
                float bb0 = bias[n], bb1 = bias[n + 1];
                e0 += bb0; e1 += bb1; e2 += bb0; e3 += bb1;
                *(float2*)(Cf + (size_t)mA * Nn + n)       = make_float2(e0, e1);
                *(float2*)(Cf + (size_t)(mA + 8) * Nn + n) = make_float2(e2, e3);
            }
        }
    }
}

// ---------------------------------------------------------------------------
// vk via tensor cores, split-K x2 (unchanged).
// ---------------------------------------------------------------------------
__global__ __launch_bounds__(128) void vk_mma_kernel(
    const __half* __restrict__ qkvh, float* __restrict__ vkp)
{
    constexpr int STAGEH = 2 * 128 * 40;
    extern __shared__ char smraw[];
    const uint32_t sbase = smem_u32(smraw);

    const int bid = blockIdx.x;
    const int head = bid >> 1;
    const int half = bid & 1;
    const int b = head >> 5;
    const int hh = head & 31;
    const int tid = threadIdx.x;
    const int wid = tid >> 5;
    const int lane = tid & 31;
    const int grp = lane >> 3;
    const int lr = lane & 7;

    float acc[3][4][4];
#pragma unroll
    for (int mt = 0; mt < 3; mt++)
#pragma unroll
        for (int nt = 0; nt < 4; nt++)
#pragma unroll
            for (int j = 0; j < 4; j++) acc[mt][nt][j] = 0.f;

    const uint32_t ones = (lane < 4) ? 0x3C003C00u : 0u;
    const uint32_t aden[4] = {ones, 0u, ones, 0u};

    auto stage = [&](int it, int s) {
        const size_t tokbase = (size_t)b * Nx + (size_t)it * 128;
#pragma unroll
        for (int j = 0; j < 8; j++) {
            int idx = tid + j * 128;
            int kv = idx >> 9;
            int r = (idx >> 2) & 127;
            int c = idx & 3;
            const __half* gp = qkvh + (tokbase + r) * NC3
                               + (kv ? 2048 : 1024) + hh * 32 + c * 8;
            uint32_t dst = sbase + (uint32_t)(s * STAGEH + kv * 5120
                                              + r * 40 + c * 8) * 2;
            cpa16(dst, gp);
        }
        asm volatile("cp.async.commit_group;" ::: "memory");
    };

    const int it0 = half * 16;
    const int it1 = it0 + 16;
    stage(it0, it0 & 1);

    for (int it = it0; it < it1; it++) {
        if (it + 1 < it1) {
            stage(it + 1, (it + 1) & 1);
            asm volatile("cp.async.wait_group 1;" ::: "memory");
        } else {
            asm volatile("cp.async.wait_group 0;" ::: "memory");
        }
        __syncthreads();

        const int s = it & 1;
        const uint32_t ks0 = sbase + (uint32_t)(s * STAGEH) * 2;
        const uint32_t vs0 = ks0 + 5120 * 2;

#pragma unroll
        for (int step = 0; step < 2; step++) {
            const int tok0 = wid * 32 + step * 16;
            uint32_t av[2][4];
#pragma unroll
            for (int mt = 0; mt < 2; mt++) {
                uint32_t ao = vs0 + (uint32_t)((tok0 + (grp >> 1) * 8 + lr) * 40
                                               + mt * 16 + (grp & 1) * 8) * 2;
                ldsm4t(av[mt][0], av[mt][1], av[mt][2], av[mt][3], ao);
            }
            uint32_t bk[4][2];
#pragma unroll
            for (int hf = 0; hf < 2; hf++) {
                uint32_t bo = ks0 + (uint32_t)((tok0 + (grp & 1) * 8 + lr) * 40
                                               + hf * 16 + (grp >> 1) * 8) * 2;
                uint32_t r0, r1, r2, r3;
                ldsm4t(r0, r1, r2, r3, bo);
                bk[2 * hf][0] = r0;     bk[2 * hf][1] = r1;
                bk[2 * hf + 1][0] = r2; bk[2 * hf + 1][1] = r3;
            }
#pragma unroll
            for (int nt = 0; nt < 4; nt++) {
#pragma unroll
                for (int mt = 0; mt < 2; mt++)
                    mma_f16(acc[mt][nt], av[mt], bk[nt][0], bk[nt][1]);
                mma_f16(acc[2][nt], aden, bk[nt][0], bk[nt][1]);
            }
        }
        __syncthreads();
    }

    float* red = (float*)smraw;
    const int g4 = lane >> 2;
    const int tig = lane & 3;
#pragma unroll
    for (int mt = 0; mt < 3; mt++)
#pragma unroll
        for (int nt = 0; nt < 4; nt++) {
            int m = mt * 16 + g4;
            int e = nt * 8 + 2 * tig;
            float* rb = red + (size_t)wid * 1584;
            rb[m * 33 + e]           = acc[mt][nt][0];
            rb[m * 33 + e + 1]       = acc[mt][nt][1];
            rb[(m + 8) * 33 + e]     = acc[mt][nt][2];
            rb[(m + 8) * 33 + e + 1] = acc[mt][nt][3];
        }
    __syncthreads();

#pragma unroll
    for (int i = 0; i < 12; i++) {
        int idx = tid + i * 128;
        int m = idx >> 5;
        int e = idx & 31;
        float s = red[m * 33 + e] + red[1584 + m * 33 + e]
                + red[2 * 1584 + m * 33 + e] + red[3 * 1584 + m * 33 + e];
        vkp[(size_t)bid * 1536 + idx] = s;
    }
}

// ---------------------------------------------------------------------------
// att via mma.sync: 256 threads, 256 tokens per CTA (unchanged from R15).
// ---------------------------------------------------------------------------
__global__ __launch_bounds__(256) void att_kernel(
    const __half* __restrict__ qkvh, const float* __restrict__ vkp,
    uint32_t* __restrict__ ath)
{
    const int blk = blockIdx.x;
    const int nch = blk & 15;
    const int head = blk >> 4;
    const int b = head >> 5;
    const int hh = head & 31;
    const int tid = threadIdx.x;
    const int wid = tid >> 5;
    const int lane = tid & 31;

    __shared__ __half qs[256][40];
    __shared__ __half vkh[48][40];

    const size_t rowbase = (size_t)b * Nx + (size_t)nch * 256;

#pragma unroll
    for (int i = 0; i < 16; i++) {
        int idx = i * 256 + tid;
        int row = idx >> 4;
        int c = idx & 15;
        uint32_t w = *(const uint32_t*)(qkvh + (rowbase + row) * NC3 + hh * 32 + 2 * c);
        *(uint32_t*)&qs[row][2 * c] = w;
    }
    const float* p0 = vkp + (size_t)(2 * head) * 1536;
    const float* p1 = p0 + 1536;
#pragma unroll
    for (int i = 0; i < 6; i++) {
        int idx = i * 256 + tid;
        int m = idx >> 5;
        int e = idx & 31;
        vkh[m][e] = __float2half_rn(p0[idx] + p1[idx]);
    }
    __syncthreads();

    const uint32_t lrow = (uint32_t)(lane & 15);
    const uint32_t lchk = (uint32_t)(lane >> 4) * 16;
    const uint32_t qsb = smem_u32(qs);
    const uint32_t vkb = smem_u32(vkh);

    uint32_t a[2][2][4];
#pragma unroll
    for (int mt = 0; mt < 2; mt++)
#pragma unroll
        for (int kk = 0; kk < 2; kk++) {
            uint32_t ao = qsb + (uint32_t)((wid * 32 + mt * 16 + lrow) * 80) + lchk + kk * 32;
            ldsm4(a[mt][kk][0], a[mt][kk][1], a[mt][kk][2], a[mt][kk][3], ao);
        }
    uint32_t bfr[6][2][2];
#pragma unroll
    for (int p = 0; p < 3; p++)
#pragma unroll
        for (int kk = 0; kk < 2; kk++) {
            uint32_t bo = vkb + (uint32_t)((p * 16 + lrow) * 80) + lchk + kk * 32;
            uint32_t r0, r1, r2, r3;
            ldsm4(r0, r1, r2, r3, bo);
            bfr[2 * p][kk][0] = r0;     bfr[2 * p][kk][1] = r2;
            bfr[2 * p + 1][kk][0] = r1; bfr[2 * p + 1][kk][1] = r3;
        }

    float c[2][5][4];
#pragma unroll
    for (int mt = 0; mt < 2; mt++)
#pragma unroll
        for (int nt = 0; nt < 5; nt++) {
#pragma unroll
            for (int j = 0; j < 4; j++) c[mt][nt][j] = 0.f;
#pragma unroll
            for (int kk = 0; kk < 2; kk++)
                mma_f16(c[mt][nt], a[mt][kk], bfr[nt][kk][0], bfr[nt][kk][1]);
        }

    const int g = lane >> 2;
    const int tig = lane & 3;
#pragma unroll
    for (int mt = 0; mt < 2; mt++) {
        float d0 = __shfl_sync(0xffffffffu, c[mt][4][0], lane & 28);
        float d1 = __shfl_sync(0xffffffffu, c[mt][4][2], lane & 28);
        float i0 = 1.0f / (d0 + EPSV);
        float i1 = 1.0f / (d1 + EPSV);
        size_t t0 = rowbase + (size_t)(wid * 32 + mt * 16 + g);
#pragma unroll
        for (int nt = 0; nt < 4; nt++) {
            __half2 h0 = __halves2half2(__float2half_rn(c[mt][nt][0] * i0),
                                        __float2half_rn(c[mt][nt][1] * i0));
            __half2 h1 = __halves2half2(__float2half_rn(c[mt][nt][2] * i1),
                                        __float2half_rn(c[mt][nt][3] * i1));
            ath[t0 * 512 + hh * 16 + nt * 4 + tig]       = *(uint32_t*)&h0;
            ath[(t0 + 8) * 512 + hh * 16 + nt * 4 + tig] = *(uint32_t*)&h1;
        }
    }
}

// ---------------------------------------------------------------------------
extern "C" void kernel_launch(void* const* d_in, const int* in_sizes, int n_in,
                              void* d_out, int out_size)
{
    const float* x     = (const float*)d_in[0];
    const float* Wqkv  = (const float*)d_in[1];
    const float* Wproj = (const float*)d_in[2];
    const float* bproj = (const float*)d_in[3];
    float* out = (float*)d_out;

    __half* qkvh;
    float* vkp;
    uint32_t *xh, *ath, *wqh, *wph;
    cudaGetSymbolAddress((void**)&qkvh, g_qkvh);
    cudaGetSymbolAddress((void**)&vkp,  g_vkp);
    cudaGetSymbolAddress((void**)&xh,   g_xh);
    cudaGetSymbolAddress((void**)&ath,  g_ath);
    cudaGetSymbolAddress((void**)&wqh,  g_wqh);
    cudaGetSymbolAddress((void**)&wph,  g_wph);

    const int M = Bx * Nx;   // 16384

    const int smem = 3 * 2 * 18432;   // 110592 B per CTA (2 CTAs/SM)
    cudaFuncSetAttribute(f16_gemm<0>,
                         cudaFuncAttributeMaxDynamicSharedMemorySize, smem);
    cudaFuncSetAttribute(f16_gemm<1>,
                         cudaFuncAttributeMaxDynamicSharedMemorySize, smem);

    // 0) fused operand prep (fp32 -> fp16), 4 floats per thread
    {
        int ngx = M * Cx / 4;
        int ngq = NC3 * Cx / 4;
        int ngp = Cx * Cx / 4;
        int tot = ngx + ngq + ngp;
        prep_kernel<<<(tot + 255) / 256, 256>>>(x, xh, ngx, Wqkv, wqh, ngq,
                                                Wproj, wph, ngp);
    }

    // 1) qkv = x @ Wqkv^T -> fp16 (relu fused on n < 2048)
    f16_gemm<0><<<dim3(NC3 / 128, M / 128), 256, smem>>>(
        xh, wqh, qkvh, nullptr, M, NC3, Cx, 2 * Cx);

    // 2) vk split-K x2 -> fp32 partials
    vk_mma_kernel<<<256, 128, 40960>>>(qkvh, vkp);

    // 3) attention normalize (256 tokens/CTA) -> ath fp16
    att_kernel<<<2048, 256>>>(qkvh, vkp, ath);

    // 4) out = att @ Wproj^T + b  (fp32 out)
    f16_gemm<1><<<dim3(Cx / 128, M / 128), 256, smem>>>(
        ath, wph, out, bproj, M, Cx, Cx, 0);
}

// round 17
// speedup vs baseline: 2.2548x; 1.0002x over previous
#include <cuda_runtime.h>
#include <cuda_fp16.h>
#include <cstdint>

#define Bx 4
#define Nx 4096
#define Cx 1024
#define NC3 3072
#define EPSV 1e-15f

// Scratch (device globals — no allocation allowed)
__device__ __half   g_qkvh[(size_t)Bx * Nx * NC3];         // 96 MB fp16 qkv
__device__ uint32_t g_xh[(size_t)Bx * Nx * Cx / 2];        // x fp16
__device__ uint32_t g_ath[(size_t)Bx * Nx * Cx / 2];       // att fp16
__device__ uint32_t g_wqh[(size_t)NC3 * Cx / 2];           // Wqkv fp16
__device__ uint32_t g_wph[(size_t)Cx * Cx / 2];            // Wproj fp16
__device__ float    g_vkp[256 * 1536];                     // vk fp32 partials

__device__ __forceinline__ uint32_t smem_u32(const void* p) {
    uint32_t a;
    asm("{ .reg .u64 t; cvta.to.shared.u64 t, %1; cvt.u32.u64 %0, t; }"
        : "=r"(a) : "l"(p));
    return a;
}
__device__ __forceinline__ void cpa16(uint32_t s, const void* g) {
    asm volatile("cp.async.cg.shared.global [%0], [%1], 16;"
                 :: "r"(s), "l"(g) : "memory");
}
__device__ __forceinline__ void ldsm4(uint32_t& r0, uint32_t& r1,
                                      uint32_t& r2, uint32_t& r3, uint32_t a) {
    asm volatile("ldmatrix.sync.aligned.m8n8.x4.shared.b16 {%0,%1,%2,%3}, [%4];"
                 : "=r"(r0), "=r"(r1), "=r"(r2), "=r"(r3) : "r"(a));
}
__device__ __forceinline__ void ldsm4t(uint32_t& r0, uint32_t& r1,
                                       uint32_t& r2, uint32_t& r3, uint32_t a) {
    asm volatile("ldmatrix.sync.aligned.m8n8.x4.trans.shared.b16 {%0,%1,%2,%3}, [%4];"
                 : "=r"(r0), "=r"(r1), "=r"(r2), "=r"(r3) : "r"(a));
}
__device__ __forceinline__ void mma_f16(float d[4], const uint32_t a[4],
                                        uint32_t b0, uint32_t b1) {
    asm("mma.sync.aligned.m16n8k16.row.col.f32.f16.f16.f32 "
        "{%0,%1,%2,%3}, {%4,%5,%6,%7}, {%8,%9}, {%0,%1,%2,%3};"
        : "+f"(d[0]), "+f"(d[1]), "+f"(d[2]), "+f"(d[3])
        : "r"(a[0]), "r"(a[1]), "r"(a[2]), "r"(a[3]), "r"(b0), "r"(b1));
}

// fused operand prep: three fp32->fp16 segments, 4 floats (2 pairs)/thread
__global__ void prep_kernel(const float* __restrict__ x,  uint32_t* __restrict__ xh,  int ngx,
                            const float* __restrict__ wq, uint32_t* __restrict__ wqh, int ngq,
                            const float* __restrict__ wp, uint32_t* __restrict__ wph, int ngp)
{
    int i = blockIdx.x * 256 + threadIdx.x;
    const float* in;
    uint32_t* out;
    int j;
    if (i < ngx)                  { in = x;  out = xh;  j = i; }
    else if (i < ngx + ngq)       { in = wq; out = wqh; j = i - ngx; }
    else if (i < ngx + ngq + ngp) { in = wp; out = wph; j = i - ngx - ngq; }
    else return;
    float4 v = ((const float4*)in)[j];
    __half2 h0 = __halves2half2(__float2half_rn(v.x), __float2half_rn(v.y));
    __half2 h1 = __halves2half2(__float2half_rn(v.z), __float2half_rn(v.w));
    uint2 o;
    o.x = *(uint32_t*)&h0;
    o.y = *(uint32_t*)&h1;
    ((uint2*)out)[j] = o;
}

// ---------------------------------------------------------------------------
// fp16 GEMM:  C[m,n] = sum_k A[m,k]*W[n,k]   (both single-rounded fp16)
// CTA 128x128x64, 8 warps (4m x 2n), warp tile 32x64, ldmatrix,
// 3-stage cp.async, ONE barrier per 64-K, 2 CTAs/SM.
// MODE 0: relu on n<relu_upto, OUTPUT fp16.  MODE 1: +bias, fp32 out.
// ---------------------------------------------------------------------------
template <int MODE>
__global__ __launch_bounds__(256, 2) void f16_gemm(
    const uint32_t* __restrict__ Ah_, const uint32_t* __restrict__ Wh_,
    void* __restrict__ Cv, const float* __restrict__ bias,
    int M, int Nn, int K, int relu_upto)
{
    constexpr int PITCH = 144;                       // 64 halfs + 8 pad (bytes)
    constexpr int A_TILE = 128 * PITCH;              // 18432
    constexpr int OFF_B  = A_TILE;
    constexpr int STAGE  = 2 * A_TILE;               // 36864
    extern __shared__ char smem[];
    const uint32_t sb = smem_u32(smem);

    const int tid = threadIdx.x;
    const int wid = tid >> 5;
    const int lane = tid & 31;
    const int g = lane >> 2;
    const int tig = lane & 3;
    const int warp_m = (wid & 3) * 32;
    const int warp_n = (wid >> 2) * 64;
    const int m0 = blockIdx.y * 128;
    const int n0 = blockIdx.x * 128;

    const __half* Ah = (const __half*)Ah_;
    const __half* Wh = (const __half*)Wh_;

    float acc[2][8][4];
#pragma unroll
    for (int mt = 0; mt < 2; mt++)
#pragma unroll
        for (int nt = 0; nt < 8; nt++)
#pragma unroll
            for (int j = 0; j < 4; j++) acc[mt][nt][j] = 0.0f;

    const int NK = K / 64;                           // 64-K tiles
    const int crow = tid >> 3;                       // 0..31
    const int cchk = tid & 7;                        // 16B chunk (8 halfs)

    auto issue = [&](int it, int s) {
        const int kt = it * 64 + cchk * 8;
        const uint32_t st = sb + (uint32_t)s * STAGE;
#pragma unroll
        for (int i = 0; i < 4; i++) {
            int r = crow + i * 32;
            uint32_t so = (uint32_t)(r * PITCH + cchk * 16);
            cpa16(st + so, Ah + (size_t)(m0 + r) * K + kt);
            cpa16(st + OFF_B + so, Wh + (size_t)(n0 + r) * K + kt);
        }
        asm volatile("cp.async.commit_group;" ::: "memory");
    };

    issue(0, 0);
    if (NK > 1) issue(1, 1);

    const uint32_t lrow = (uint32_t)(lane & 15);
    const uint32_t lchk = (uint32_t)(lane >> 4) * 16;

    for (int it = 0; it < NK; it++) {
        if (it + 1 < NK) {
            asm volatile("cp.async.wait_group 1;" ::: "memory");
        } else {
            asm volatile("cp.async.wait_group 0;" ::: "memory");
        }
        __syncthreads();
        if (it + 2 < NK) issue(it + 2, (it + 2) % 3);

        const uint32_t st = sb + (uint32_t)(it % 3) * STAGE;
        const uint32_t abase = st + (uint32_t)(warp_m + lrow) * PITCH + lchk;
        const uint32_t bbase = st + OFF_B + (uint32_t)(warp_n + lrow) * PITCH + lchk;

#pragma unroll
        for (int kk = 0; kk < 4; kk++) {
            uint32_t ah[2][4];
#pragma unroll
            for (int mt = 0; mt < 2; mt++) {
                uint32_t ao = abase + (uint32_t)(mt * 16 * PITCH + kk * 32);
                ldsm4(ah[mt][0], ah[mt][1], ah[mt][2], ah[mt][3], ao);
            }
            uint32_t b[8][2];
#pragma unroll
            for (int p = 0; p < 4; p++) {
                uint32_t bo = bbase + (uint32_t)(p * 16 * PITCH + kk * 32);
                uint32_t r0, r1, r2, r3;
                ldsm4(r0, r1, r2, r3, bo);
                b[2 * p][0] = r0; b[2 * p][1] = r2;
                b[2 * p + 1][0] = r1; b[2 * p + 1][1] = r3;
            }
#pragma unroll
            for (int nt = 0; nt < 8; nt++)
#pragma unroll
                for (int mt = 0; mt < 2; mt++)
                    mma_f16(acc[mt][nt], ah[mt], b[nt][0], b[nt][1]);
        }
    }

    // epilogue
#pragma unroll
    for (int mt = 0; mt < 2; mt++) {
        int mA = m0 + warp_m + mt * 16 + g;
#pragma unroll
        for (int nt = 0; nt < 8; nt++) {
            int n = n0 + warp_n + nt * 8 + 2 * tig;
            float e0 = acc[mt][nt][0], e1 = acc[mt][nt][1];
            float e2 = acc[mt][nt][2], e3 = acc[mt][nt][3];
            if (MODE == 0) {
                if (n < relu_upto)     { e0 = fmaxf(e0, 0.f); e2 = fmaxf(e2, 0.f); }
                if (n + 1 < relu_upto) { e1 = fmaxf(e1, 0.f); e3 = fmaxf(e3, 0.f); }
                __half* Ch = (__half*)Cv;
                __half2 h01 = __halves2half2(__float2half_rn(e0), __float2half_rn(e1));
                __half2 h23 = __halves2half2(__float2half_rn(e2), __float2half_rn(e3));
                *(uint32_t*)(Ch + (size_t)mA * Nn + n)       = *(uint32_t*)&h01;
                *(uint32_t*)(Ch + (size_t)(mA + 8) * Nn + n) = *(uint32_t*)&h23;
            } else {
                float* Cf = (float*)Cv;
                float bb0 = bias[n], bb1 = bias[n + 1];
                e0 += bb0; e1 += bb1; e2 += bb0; e3 += bb1;
                *(float2*)(Cf + (size_t)mA * Nn + n)       = make_float2(e0, e1);
                *(float2*)(Cf + (size_t)(mA + 8) * Nn + n) = make_float2(e2, e3);
            }
        }
    }
}

// ---------------------------------------------------------------------------
// vk via tensor cores, split-K x2 (unchanged).
// ---------------------------------------------------------------------------
__global__ __launch_bounds__(128) void vk_mma_kernel(
    const __half* __restrict__ qkvh, float* __restrict__ vkp)
{
    constexpr int STAGEH = 2 * 128 * 40;
    extern __shared__ char smraw[];
    const uint32_t sbase = smem_u32(smraw);

    const int bid = blockIdx.x;
    const int head = bid >> 1;
    const int half = bid & 1;
    const int b = head >> 5;
    const int hh = head & 31;
    const int tid = threadIdx.x;
    const int wid = tid >> 5;
    const int lane = tid & 31;
    const int grp = lane >> 3;
    const int lr = lane & 7;

    float acc[3][4][4];
#pragma unroll
    for (int mt = 0; mt < 3; mt++)
#pragma unroll
        for (int nt = 0; nt < 4; nt++)
#pragma unroll
            for (int j = 0; j < 4; j++) acc[mt][nt][j] = 0.f;

    const uint32_t ones = (lane < 4) ? 0x3C003C00u : 0u;
    const uint32_t aden[4] = {ones, 0u, ones, 0u};

    auto stage = [&](int it, int s) {
        const size_t tokbase = (size_t)b * Nx + (size_t)it * 128;
#pragma unroll
        for (int j = 0; j < 8; j++) {
            int idx = tid + j * 128;
            int kv = idx >> 9;
            int r = (idx >> 2) & 127;
            int c = idx & 3;
            const __half* gp = qkvh + (tokbase + r) * NC3
                               + (kv ? 2048 : 1024) + hh * 32 + c * 8;
            uint32_t dst = sbase + (uint32_t)(s * STAGEH + kv * 5120
                                              + r * 40 + c * 8) * 2;
            cpa16(dst, gp);
        }
        asm volatile("cp.async.commit_group;" ::: "memory");
    };

    const int it0 = half * 16;
    const int it1 = it0 + 16;
    stage(it0, it0 & 1);

    for (int it = it0; it < it1; it++) {
        if (it + 1 < it1) {
            stage(it + 1, (it + 1) & 1);
            asm volatile("cp.async.wait_group 1;" ::: "memory");
        } else {
            asm volatile("cp.async.wait_group 0;" ::: "memory");
        }
        __syncthreads();

        const int s = it & 1;
        const uint32_t ks0 = sbase + (uint32_t)(s * STAGEH) * 2;
        const uint32_t vs0 = ks0 + 5120 * 2;

#pragma unroll
        for (int step = 0; step < 2; step++) {
            const int tok0 = wid * 32 + step * 16;
            uint32_t av[2][4];
#pragma unroll
            for (int mt = 0; mt < 2; mt++) {
                uint32_t ao = vs0 + (uint32_t)((tok0 + (grp >> 1) * 8 + lr) * 40
                                               + mt * 16 + (grp & 1) * 8) * 2;
                ldsm4t(av[mt][0], av[mt][1], av[mt][2], av[mt][3], ao);
            }
            uint32_t bk[4][2];
#pragma unroll
            for (int hf = 0; hf < 2; hf++) {
                uint32_t bo = ks0 + (uint32_t)((tok0 + (grp & 1) * 8 + lr) * 40
                                               + hf * 16 + (grp >> 1) * 8) * 2;
                uint32_t r0, r1, r2, r3;
                ldsm4t(r0, r1, r2, r3, bo);
                bk[2 * hf][0] = r0;     bk[2 * hf][1] = r1;
                bk[2 * hf + 1][0] = r2; bk[2 * hf + 1][1] = r3;
            }
#pragma unroll
            for (int nt = 0; nt < 4; nt++) {
#pragma unroll
                for (int mt = 0; mt < 2; mt++)
                    mma_f16(acc[mt][nt], av[mt], bk[nt][0], bk[nt][1]);
                mma_f16(acc[2][nt], aden, bk[nt][0], bk[nt][1]);
            }
        }
        __syncthreads();
    }

    float* red = (float*)smraw;
    const int g4 = lane >> 2;
    const int tig = lane & 3;
#pragma unroll
    for (int mt = 0; mt < 3; mt++)
#pragma unroll
        for (int nt = 0; nt < 4; nt++) {
            int m = mt * 16 + g4;
            int e = nt * 8 + 2 * tig;
            float* rb = red + (size_t)wid * 1584;
            rb[m * 33 + e]           = acc[mt][nt][0];
            rb[m * 33 + e + 1]       = acc[mt][nt][1];
            rb[(m + 8) * 33 + e]     = acc[mt][nt][2];
            rb[(m + 8) * 33 + e + 1] = acc[mt][nt][3];
        }
    __syncthreads();

#pragma unroll
    for (int i = 0; i < 12; i++) {
        int idx = tid + i * 128;
        int m = idx >> 5;
        int e = idx & 31;
        float s = red[m * 33 + e] + red[1584 + m * 33 + e]
                + red[2 * 1584 + m * 33 + e] + red[3 * 1584 + m * 33 + e];
        vkp[(size_t)bid * 1536 + idx] = s;
    }
}

// ---------------------------------------------------------------------------
// att via mma.sync: 256 threads, 256 tokens per CTA (unchanged from R15).
// ---------------------------------------------------------------------------
__global__ __launch_bounds__(256) void att_kernel(
    const __half* __restrict__ qkvh, const float* __restrict__ vkp,
    uint32_t* __restrict__ ath)
{
    const int blk = blockIdx.x;
    const int nch = blk & 15;
    const int head = blk >> 4;
    const int b = head >> 5;
    const int hh = head & 31;
    const int tid = threadIdx.x;
    const int wid = tid >> 5;
    const int lane = tid & 31;

    __shared__ __half qs[256][40];
    __shared__ __half vkh[48][40];

    const size_t rowbase = (size_t)b * Nx + (size_t)nch * 256;

#pragma unroll
    for (int i = 0; i < 16; i++) {
        int idx = i * 256 + tid;
        int row = idx >> 4;
        int c = idx & 15;
        uint32_t w = *(const uint32_t*)(qkvh + (rowbase + row) * NC3 + hh * 32 + 2 * c);
        *(uint32_t*)&qs[row][2 * c] = w;
    }
    const float* p0 = vkp + (size_t)(2 * head) * 1536;
    const float* p1 = p0 + 1536;
#pragma unroll
    for (int i = 0; i < 6; i++) {
        int idx = i * 256 + tid;
        int m = idx >> 5;
        int e = idx & 31;
        vkh[m][e] = __float2half_rn(p0[idx] + p1[idx]);
    }
    __syncthreads();

    const uint32_t lrow = (uint32_t)(lane & 15);
    const uint32_t lchk = (uint32_t)(lane >> 4) * 16;
    const uint32_t qsb = smem_u32(qs);
    const uint32_t vkb = smem_u32(vkh);

    uint32_t a[2][2][4];
#pragma unroll
    for (int mt = 0; mt < 2; mt++)
#pragma unroll
        for (int kk = 0; kk < 2; kk++) {
            uint32_t ao = qsb + (uint32_t)((wid * 32 + mt * 16 + lrow) * 80) + lchk + kk * 32;
            ldsm4(a[mt][kk][0], a[mt][kk][1], a[mt][kk][2], a[mt][kk][3], ao);
        }
    uint32_t bfr[6][2][2];
#pragma unroll
    for (int p = 0; p < 3; p++)
#pragma unroll
        for (int kk = 0; kk < 2; kk++) {
            uint32_t bo = vkb + (uint32_t)((p * 16 + lrow) * 80) + lchk + kk * 32;
            uint32_t r0, r1, r2, r3;
            ldsm4(r0, r1, r2, r3, bo);
            bfr[2 * p][kk][0] = r0;     bfr[2 * p][kk][1] = r2;
            bfr[2 * p + 1][kk][0] = r1; bfr[2 * p + 1][kk][1] = r3;
        }

    float c[2][5][4];
#pragma unroll
    for (int mt = 0; mt < 2; mt++)
#pragma unroll
        for (int nt = 0; nt < 5; nt++) {
#pragma unroll
            for (int j = 0; j < 4; j++) c[mt][nt][j] = 0.f;
#pragma unroll
            for (int kk = 0; kk < 2; kk++)
                mma_f16(c[mt][nt], a[mt][kk], bfr[nt][kk][0], bfr[nt][kk][1]);
        }

    const int g = lane >> 2;
    const int tig = lane & 3;
#pragma unroll
    for (int mt = 0; mt < 2; mt++) {
        float d0 = __shfl_sync(0xffffffffu, c[mt][4][0], lane & 28);
        float d1 = __shfl_sync(0xffffffffu, c[mt][4][2], lane & 28);
        float i0 = 1.0f / (d0 + EPSV);
        float i1 = 1.0f / (d1 + EPSV);
        size_t t0 = rowbase + (size_t)(wid * 32 + mt * 16 + g);
#pragma unroll
        for (int nt = 0; nt < 4; nt++) {
            __half2 h0 = __halves2half2(__float2half_rn(c[mt][nt][0] * i0),
                                        __float2half_rn(c[mt][nt][1] * i0));
            __half2 h1 = __halves2half2(__float2half_rn(c[mt][nt][2] * i1),
                                        __float2half_rn(c[mt][nt][3] * i1));
            ath[t0 * 512 + hh * 16 + nt * 4 + tig]       = *(uint32_t*)&h0;
            ath[(t0 + 8) * 512 + hh * 16 + nt * 4 + tig] = *(uint32_t*)&h1;
        }
    }
}

// ---------------------------------------------------------------------------
extern "C" void kernel_launch(void* const* d_in, const int* in_sizes, int n_in,
                              void* d_out, int out_size)
{
    const float* x     = (const float*)d_in[0];
    const float* Wqkv  = (const float*)d_in[1];
    const float* Wproj = (const float*)d_in[2];
    const float* bproj = (const float*)d_in[3];
    float* out = (float*)d_out;

    __half* qkvh;
    float* vkp;
    uint32_t *xh, *ath, *wqh, *wph;
    cudaGetSymbolAddress((void**)&qkvh, g_qkvh);
    cudaGetSymbolAddress((void**)&vkp,  g_vkp);
    cudaGetSymbolAddress((void**)&xh,   g_xh);
    cudaGetSymbolAddress((void**)&ath,  g_ath);
    cudaGetSymbolAddress((void**)&wqh,  g_wqh);
    cudaGetSymbolAddress((void**)&wph,  g_wph);

    const int M = Bx * Nx;   // 16384

    const int smem = 3 * 2 * 18432;   // 110592 B per CTA (2 CTAs/SM)
    cudaFuncSetAttribute(f16_gemm<0>,
                         cudaFuncAttributeMaxDynamicSharedMemorySize, smem);
    cudaFuncSetAttribute(f16_gemm<1>,
                         cudaFuncAttributeMaxDynamicSharedMemorySize, smem);

    // 0) fused operand prep (fp32 -> fp16), 4 floats per thread
    {
        int ngx = M * Cx / 4;
        int ngq = NC3 * Cx / 4;
        int ngp = Cx * Cx / 4;
        int tot = ngx + ngq + ngp;
        prep_kernel<<<(tot + 255) / 256, 256>>>(x, xh, ngx, Wqkv, wqh, ngq,
                                                Wproj, wph, ngp);
    }

    // 1) qkv = x @ Wqkv^T -> fp16 (relu fused on n < 2048)
    f16_gemm<0><<<dim3(NC3 / 128, M / 128), 256, smem>>>(
        xh, wqh, qkvh, nullptr, M, NC3, Cx, 2 * Cx);

    // 2) vk split-K x2 -> fp32 partials
    vk_mma_kernel<<<256, 128, 40960>>>(qkvh, vkp);

    // 3) attention normalize (256 tokens/CTA) -> ath fp16
    att_kernel<<<2048, 256>>>(qkvh, vkp, ath);

    // 4) out = att @ Wproj^T + b  (fp32 out)
    f16_gemm<1><<<dim3(Cx / 128, M / 128), 256, smem>>>(
        ath, wph, out, bproj, M, Cx, Cx, 0);
}